// round 6
// baseline (speedup 1.0000x reference)
#include <cuda_runtime.h>
#include <cuda_bf16.h>
#include <math.h>

#define E    512
#define HH   1536
#define G4   6144
#define SS   32
#define TT   48
#define NV   128
#define NB   128       // persistent blocks (1/SM)
#define NT   768       // 24 warps
#define NW   24
#define UPB  12        // h2/c2 units per block
#define WELEM      (G4 * HH)
#define WOUT_ELEMS (TT * SS * HH)

// ---------------- persistent device state ----------------
__device__ float          g_xproj[NV * G4];            // W_ih1@emb[v] + b_ih1 + b_hh1
__device__ float          g_b2sum[G4];                 // b_ih2 + b_hh2
__device__ __nv_bfloat16  g_w2cat[(size_t)G4 * 2 * HH];// [W_ih2 | W_hh2] rows of 3072
__device__ __nv_bfloat16  g_whh1[WELEM];
__device__ __nv_bfloat16  g_woutb[WOUT_ELEMS];         // bf16 head
__device__ float          g_c1[2][HH];
__device__ float          g_c2[HH];
__device__ float          g_h2[2][HH];
__device__ float          g_g1[2][G4];                 // W_hh1 @ h1(t), double buffered
__device__ float          g_lpart[NB * SS];            // per-block partial logits
__device__ unsigned       g_bar;

__device__ __forceinline__ float fsigm(float x) {
    return __fdividef(1.0f, 1.0f + __expf(-x));
}
__device__ __forceinline__ float ftanh(float x) {
    x = fminf(fmaxf(x, -15.0f), 15.0f);
    float e = __expf(2.0f * x);
    return __fdividef(e - 1.0f, e + 1.0f);
}
__device__ __forceinline__ float warpsum(float v) {
    #pragma unroll
    for (int o = 16; o; o >>= 1) v += __shfl_down_sync(0xffffffffu, v, o);
    return v;
}

// NR consecutive bf16 rows (stride elems), accumulate into acc[] (caller inits).
// SEGS segments of 256 elems (8 per lane).
template<int NR, int SEGS>
__device__ __forceinline__ void dotN_acc(const __nv_bfloat16* __restrict__ base,
                                         size_t stride, const float* __restrict__ sv,
                                         int lane, float* acc) {
    #pragma unroll
    for (int j = 0; j < SEGS; j++) {
        int seg = lane + 32 * j;
        const float4* v = (const float4*)(sv + seg * 8);
        float4 v0 = v[0], v1 = v[1];
        #pragma unroll
        for (int r = 0; r < NR; r++) {
            uint4 a = __ldg((const uint4*)(base + r * stride) + seg);
            float2 p;
            p = __bfloat1622float2(*(const __nv_bfloat162*)&a.x);
            acc[r] = fmaf(p.x, v0.x, acc[r]); acc[r] = fmaf(p.y, v0.y, acc[r]);
            p = __bfloat1622float2(*(const __nv_bfloat162*)&a.y);
            acc[r] = fmaf(p.x, v0.z, acc[r]); acc[r] = fmaf(p.y, v0.w, acc[r]);
            p = __bfloat1622float2(*(const __nv_bfloat162*)&a.z);
            acc[r] = fmaf(p.x, v1.x, acc[r]); acc[r] = fmaf(p.y, v1.y, acc[r]);
            p = __bfloat1622float2(*(const __nv_bfloat162*)&a.w);
            acc[r] = fmaf(p.x, v1.z, acc[r]); acc[r] = fmaf(p.y, v1.w, acc[r]);
        }
    }
}

__device__ __forceinline__ void grid_sync(unsigned target) {
    __threadfence();
    __syncthreads();
    if (threadIdx.x == 0) {
        atomicAdd(&g_bar, 1u);
        while (*(volatile unsigned*)&g_bar < target) { }
        __threadfence();
    }
    __syncthreads();
}

// ---------------- init ----------------
__global__ void init_kernel(const float* __restrict__ b_ih2,
                            const float* __restrict__ b_hh2) {
    int tid = threadIdx.x;  // 1024
    if (tid == 0) g_bar = 0u;
    for (int i = tid; i < HH; i += 1024) {
        g_c2[i]    = 0.0f;
        g_h2[0][i] = 0.0f;   // h2(-1)
    }
    for (int i = tid; i < G4; i += 1024) g_b2sum[i] = b_ih2[i] + b_hh2[i];
}

// ---------------- fused fp32 -> bf16 conversions (4 jobs via blockIdx.y) ----
__global__ void __launch_bounds__(256)
cvt_all(const float* __restrict__ Wih2, const float* __restrict__ Whh2,
        const float* __restrict__ Whh1, const float* __restrict__ Wout,
        __nv_bfloat16* __restrict__ w2cat, __nv_bfloat16* __restrict__ whh1,
        __nv_bfloat16* __restrict__ woutb) {
    long i = ((long)blockIdx.x * 256 + threadIdx.x) * 8;
    int job = blockIdx.y;
    const float* src;
    __nv_bfloat16* dst;
    long nelem, stride, coloff;
    if (job == 0)      { src = Wih2; dst = w2cat; nelem = WELEM; stride = 2 * HH; coloff = 0; }
    else if (job == 1) { src = Whh2; dst = w2cat; nelem = WELEM; stride = 2 * HH; coloff = HH; }
    else if (job == 2) { src = Whh1; dst = whh1;  nelem = WELEM; stride = HH;     coloff = 0; }
    else               { src = Wout; dst = woutb; nelem = WOUT_ELEMS; stride = HH; coloff = 0; }
    if (i >= nelem) return;
    long row = i / HH, col = i % HH;
    float4 a = *(const float4*)(src + i);
    float4 b = *(const float4*)(src + i + 4);
    __nv_bfloat162 r0 = __floats2bfloat162_rn(a.x, a.y);
    __nv_bfloat162 r1 = __floats2bfloat162_rn(a.z, a.w);
    __nv_bfloat162 r2 = __floats2bfloat162_rn(b.x, b.y);
    __nv_bfloat162 r3 = __floats2bfloat162_rn(b.z, b.w);
    uint4 o;
    o.x = *(const unsigned*)&r0; o.y = *(const unsigned*)&r1;
    o.z = *(const unsigned*)&r2; o.w = *(const unsigned*)&r3;
    *(uint4*)(dst + row * stride + coloff + col) = o;
}

// ---------------- precompute xproj = W_ih1 @ emb^T + biases ----------------
__global__ void __launch_bounds__(512)
xproj_kernel(const float* __restrict__ Wih1,
             const float* __restrict__ bih1, const float* __restrict__ bhh1,
             const float* __restrict__ emb) {
    __shared__ __align__(16) float W[16 * E];
    int b   = blockIdx.x;
    int tid = threadIdx.x;
    for (int i = tid; i < 16 * E; i += 512)
        W[i] = Wih1[(size_t)b * 16 * E + i];
    __syncthreads();
    for (int o = tid; o < 16 * NV; o += 512) {
        int r = o & 15, v = o >> 4;
        const float4* ev = (const float4*)(emb + (size_t)v * E);
        const float4* wr = (const float4*)(W + r * E);
        float acc = 0.f;
        #pragma unroll 4
        for (int k = 0; k < E / 4; k++) {
            float4 a = wr[k], c = ev[k];
            acc = fmaf(a.x, c.x, acc); acc = fmaf(a.y, c.y, acc);
            acc = fmaf(a.z, c.z, acc); acc = fmaf(a.w, c.w, acc);
        }
        int row = b * 16 + r;
        g_xproj[(size_t)v * G4 + row] = acc + bih1[row] + bhh1[row];
    }
}

// ---------------- persistent controller ----------------
__global__ void __launch_bounds__(NT, 1)
nas_persist(const int*   __restrict__ input_id,
            const float* __restrict__ bout,
            float* __restrict__ out) {
    __shared__ __align__(16) float sV[2 * HH];   // [h1(t) ; h2(t-1)]
    __shared__ float sWo[SS * UPB];              // Wout[t] slice for this block's units
    __shared__ float sG[48];
    __shared__ int   sId;

    const int tid  = threadIdx.x;
    const int w    = tid >> 5;
    const int lane = tid & 31;
    const int b    = blockIdx.x;
    const int u0   = b * UPB;

    // this warp's 2 cell2 rows: local rows l=2w, 2w+1 (l = gate*12 + j)
    const int l0    = 2 * w;
    const int gate  = l0 / 12;
    const int j0    = l0 % 12;
    const int grow  = gate * HH + u0 + j0;
    const __nv_bfloat16* w2base = g_w2cat + (size_t)grow * (2 * HH);
    const int r1row = b * 48 + l0;               // whh1 rows

    for (int t = 0; t < TT; t++) {
        const int par = t & 1;

        // ---- A: stage h2(t-1); prefetch sId-independent state; Wout[t] slice
        float a0[2], a1[2], a2[2], a3[2], cc[2];
        #pragma unroll
        for (int k = 0; k < 2; k++) {
            int u = tid + k * NT;
            sV[HH + u] = g_h2[par][u];
            if (t > 0) {
                a0[k] = g_g1[par][u];          a1[k] = g_g1[par][HH + u];
                a2[k] = g_g1[par][2 * HH + u]; a3[k] = g_g1[par][3 * HH + u];
                cc[k] = g_c1[par][u];
            }
        }
        if (tid < SS * UPB) {
            int s = tid / UPB, j = tid % UPB;
            sWo[tid] = __bfloat162float(g_woutb[((size_t)t * SS + s) * HH + u0 + j]);
        }
        __syncthreads();

        // ---- B: warp0 = logits reduce + softmax + argmax; all warps: phase-A dot
        if (w == 0 && t > 0) {
            float v = 0.f;
            #pragma unroll 4
            for (int bb = 0; bb < NB; bb++) v += g_lpart[bb * SS + lane];
            v += bout[(t - 1) * SS + lane];
            float m = v;
            #pragma unroll
            for (int o = 16; o; o >>= 1) m = fmaxf(m, __shfl_xor_sync(0xffffffffu, m, o));
            float e = expf(v - m), se = e;
            #pragma unroll
            for (int o = 16; o; o >>= 1) se += __shfl_xor_sync(0xffffffffu, se, o);
            float lse = m + logf(se);
            if (b == 0) out[(t - 1) * SS + lane] = v - lse;
            float bv = v; int bi = lane;
            #pragma unroll
            for (int o = 16; o; o >>= 1) {
                float ov = __shfl_xor_sync(0xffffffffu, bv, o);
                int   oi = __shfl_xor_sync(0xffffffffu, bi, o);
                if (ov > bv || (ov == bv && oi < bi)) { bv = ov; bi = oi; }
            }
            if (lane == 0) sId = ((t - 1) & 3) * SS + bi;
        }

        float acc[2] = {0.f, 0.f};
        dotN_acc<2, 6>(w2base + HH, 2 * HH, sV + HH, lane, acc);  // W_hh2 @ h2(t-1)
        __syncthreads();   // sId ready

        // ---- C: build h1(t) redundantly; update own c1 slice
        if (t == 0) {
            int id0 = *input_id;
            const float* xp = g_xproj + (size_t)id0 * G4;
            #pragma unroll
            for (int k = 0; k < 2; k++) {
                int u = tid + k * NT;
                float gi = xp[u], gg = xp[2 * HH + u], go = xp[3 * HH + u];
                float cn = fsigm(gi) * ftanh(gg);            // c_old = 0
                sV[u] = fsigm(go) * ftanh(cn);
                if (u >= u0 && u < u0 + UPB) g_c1[1][u] = cn;
            }
        } else {
            const float* xp = g_xproj + (size_t)sId * G4;
            #pragma unroll
            for (int k = 0; k < 2; k++) {
                int u = tid + k * NT;
                float gi = a0[k] + xp[u];
                float gf = a1[k] + xp[HH + u];
                float gg = a2[k] + xp[2 * HH + u];
                float go = a3[k] + xp[3 * HH + u];
                float cn = fsigm(gf) * cc[k] + fsigm(gi) * ftanh(gg);
                sV[u] = fsigm(go) * ftanh(cn);
                if (u >= u0 && u < u0 + UPB) g_c1[par ^ 1][u] = cn;
            }
        }
        __syncthreads();

        // ---- D: phase-B dots (depend on h1)
        dotN_acc<2, 6>(w2base, 2 * HH, sV, lane, acc);            // + W_ih2 @ h1(t)
        acc[0] = warpsum(acc[0]);
        acc[1] = warpsum(acc[1]);
        if (lane == 0) {
            sG[l0]     = acc[0] + g_b2sum[grow];
            sG[l0 + 1] = acc[1] + g_b2sum[grow + 1];
        }
        {
            float r[2] = {0.f, 0.f};
            dotN_acc<2, 6>(g_whh1 + (size_t)r1row * HH, HH, sV, lane, r);
            r[0] = warpsum(r[0]);
            r[1] = warpsum(r[1]);
            if (lane == 0) {
                g_g1[par ^ 1][r1row]     = r[0];
                g_g1[par ^ 1][r1row + 1] = r[1];
            }
        }
        __syncthreads();

        // ---- E: finalize own h2 units (warp 0) + partial logits via shuffles
        if (w == 0) {
            float hn = 0.f;
            if (lane < UPB) {
                int u = u0 + lane;
                float gi = sG[lane], gf = sG[12 + lane], gg = sG[24 + lane], go = sG[36 + lane];
                float c  = g_c2[u];
                float cn = fsigm(gf) * c + fsigm(gi) * ftanh(gg);
                g_c2[u]          = cn;
                hn               = fsigm(go) * ftanh(cn);
                g_h2[par ^ 1][u] = hn;
            }
            float p = 0.f;
            #pragma unroll
            for (int j = 0; j < UPB; j++) {
                float hj = __shfl_sync(0xffffffffu, hn, j);
                p = fmaf(sWo[lane * UPB + j], hj, p);
            }
            g_lpart[b * SS + lane] = p;   // lane = s
        }
        grid_sync((unsigned)(t + 1) * NB);
    }

    // epilogue: logp(47)
    if (b == 0 && w == 0) {
        float v = 0.f;
        #pragma unroll 4
        for (int bb = 0; bb < NB; bb++) v += g_lpart[bb * SS + lane];
        v += bout[47 * SS + lane];
        float m = v;
        #pragma unroll
        for (int o = 16; o; o >>= 1) m = fmaxf(m, __shfl_xor_sync(0xffffffffu, m, o));
        float e = expf(v - m), se = e;
        #pragma unroll
        for (int o = 16; o; o >>= 1) se += __shfl_xor_sync(0xffffffffu, se, o);
        float lse = m + logf(se);
        out[47 * SS + lane] = v - lse;
    }
}

extern "C" void kernel_launch(void* const* d_in, const int* in_sizes, int n_in,
                              void* d_out, int out_size) {
    const int*   input_id = (const int*)  d_in[0];
    const float* emb      = (const float*)d_in[1];
    const float* W_ih1    = (const float*)d_in[2];
    const float* W_hh1    = (const float*)d_in[3];
    const float* b_ih1    = (const float*)d_in[4];
    const float* b_hh1    = (const float*)d_in[5];
    const float* W_ih2    = (const float*)d_in[6];
    const float* W_hh2    = (const float*)d_in[7];
    const float* b_ih2    = (const float*)d_in[8];
    const float* b_hh2    = (const float*)d_in[9];
    const float* W_out    = (const float*)d_in[10];
    const float* b_out    = (const float*)d_in[11];
    float* out = (float*)d_out;

    __nv_bfloat16* w2cat_d; cudaGetSymbolAddress((void**)&w2cat_d, g_w2cat);
    __nv_bfloat16* whh1_d;  cudaGetSymbolAddress((void**)&whh1_d,  g_whh1);
    __nv_bfloat16* woutb_d; cudaGetSymbolAddress((void**)&woutb_d, g_woutb);

    dim3 cvt_grid((WELEM / 8 + 255) / 256, 4);
    init_kernel<<<1, 1024>>>(b_ih2, b_hh2);
    cvt_all<<<cvt_grid, 256>>>(W_ih2, W_hh2, W_hh1, W_out, w2cat_d, whh1_d, woutb_d);
    xproj_kernel<<<G4 / 16, 512>>>(W_ih1, b_ih1, b_hh1, emb);
    nas_persist<<<NB, NT>>>(input_id, b_out, out);
}

// round 7
// speedup vs baseline: 1.2712x; 1.2712x over previous
#include <cuda_runtime.h>
#include <cuda_bf16.h>
#include <math.h>

#define E    512
#define HH   1536
#define G4   6144
#define SS   32
#define TT   48
#define NV   128
#define NB   128       // persistent blocks (1/SM, <=148)
#define NT   512
#define UPB  12        // h2/c2 units per block
#define WELEM      (G4 * HH)
#define WOUT_ELEMS (TT * SS * HH)

// ---------------- persistent device state ----------------
__device__ float          g_xproj[NV * G4];            // W_ih1@emb[v] + b_ih1 + b_hh1
__device__ float          g_b2sum[G4];                 // b_ih2 + b_hh2
__device__ __nv_bfloat16  g_w2cat[(size_t)G4 * 2 * HH];// [W_ih2 | W_hh2] rows of 3072
__device__ __nv_bfloat16  g_whh1[WELEM];
__device__ __nv_bfloat16  g_woutb[WOUT_ELEMS];         // bf16 head
__device__ float          g_c1[2][HH];
__device__ float          g_c2[HH];
__device__ float          g_h2[2][HH];
__device__ float          g_g1[2][G4];                 // W_hh1 @ h1(t), double buffered
__device__ unsigned       g_flags[NB];                 // per-block arrival epochs
__device__ unsigned       g_release;                   // global release epoch

// fast activations (cell path); softmax path uses exact expf/logf
__device__ __forceinline__ float fsigm(float x) {
    return __fdividef(1.0f, 1.0f + __expf(-x));
}
__device__ __forceinline__ float ftanh(float x) {
    x = fminf(fmaxf(x, -15.0f), 15.0f);
    float e = __expf(2.0f * x);
    return __fdividef(e - 1.0f, e + 1.0f);
}

__device__ __forceinline__ float warpsum(float v) {
    #pragma unroll
    for (int o = 16; o; o >>= 1) v += __shfl_down_sync(0xffffffffu, v, o);
    return v;
}

// NR consecutive bf16 rows (stride 'stride' elems), one shared pass over sv.
// SEGS segments of 256 elems (8 per lane). fp32 accumulate.
template<int NR, int SEGS>
__device__ __forceinline__ void dotN(const __nv_bfloat16* __restrict__ base,
                                     size_t stride, const float* __restrict__ sv,
                                     int lane, float* acc) {
    #pragma unroll
    for (int r = 0; r < NR; r++) acc[r] = 0.f;
    #pragma unroll
    for (int j = 0; j < SEGS; j++) {
        int seg = lane + 32 * j;
        const float4* v = (const float4*)(sv + seg * 8);
        float4 v0 = v[0], v1 = v[1];
        #pragma unroll
        for (int r = 0; r < NR; r++) {
            uint4 a = __ldg((const uint4*)(base + r * stride) + seg);
            float2 p;
            p = __bfloat1622float2(*(const __nv_bfloat162*)&a.x);
            acc[r] = fmaf(p.x, v0.x, acc[r]); acc[r] = fmaf(p.y, v0.y, acc[r]);
            p = __bfloat1622float2(*(const __nv_bfloat162*)&a.y);
            acc[r] = fmaf(p.x, v0.z, acc[r]); acc[r] = fmaf(p.y, v0.w, acc[r]);
            p = __bfloat1622float2(*(const __nv_bfloat162*)&a.z);
            acc[r] = fmaf(p.x, v1.x, acc[r]); acc[r] = fmaf(p.y, v1.y, acc[r]);
            p = __bfloat1622float2(*(const __nv_bfloat162*)&a.w);
            acc[r] = fmaf(p.x, v1.z, acc[r]); acc[r] = fmaf(p.y, v1.w, acc[r]);
        }
    }
}

// -------- contention-free grid barrier: per-block flags + single release word
__device__ __forceinline__ void grid_sync(int b, unsigned ep) {
    __threadfence();          // release all prior writes
    __syncthreads();
    if (b == 0) {
        if (threadIdx.x < NB && threadIdx.x != 0) {
            volatile unsigned* f = &g_flags[threadIdx.x];
            while (*f < ep) { __nanosleep(32); }
        }
        __syncthreads();      // all flags observed
        if (threadIdx.x == 0) {
            __threadfence();
            *(volatile unsigned*)&g_release = ep;
        }
    } else {
        if (threadIdx.x == 0) {
            *(volatile unsigned*)&g_flags[b] = ep;   // parallel arrival
            volatile unsigned* r = &g_release;
            while (*r < ep) { __nanosleep(32); }
            __threadfence();  // acquire
        }
    }
    __syncthreads();
}

// ---------------- init ----------------
__global__ void init_kernel(const float* __restrict__ b_ih2,
                            const float* __restrict__ b_hh2) {
    int tid = threadIdx.x;  // 1024
    if (tid == 0) g_release = 0u;
    if (tid < NB) g_flags[tid] = 0u;
    for (int i = tid; i < HH; i += 1024) {
        g_c2[i]    = 0.0f;
        g_h2[0][i] = 0.0f;   // h2(-1)
    }
    for (int i = tid; i < G4; i += 1024) g_b2sum[i] = b_ih2[i] + b_hh2[i];
}

// ---------------- fp32 -> bf16 (rows of HH, remapped to dst_stride) ----------
__global__ void __launch_bounds__(256)
cvt_kernel(const float* __restrict__ src, __nv_bfloat16* __restrict__ dst,
           int dst_stride, int col_off, long nelem) {
    long i = ((long)blockIdx.x * 256 + threadIdx.x) * 8;
    if (i >= nelem) return;
    long row = i / HH, col = i % HH;
    float4 a = *(const float4*)(src + i);
    float4 b = *(const float4*)(src + i + 4);
    __nv_bfloat162 r0 = __floats2bfloat162_rn(a.x, a.y);
    __nv_bfloat162 r1 = __floats2bfloat162_rn(a.z, a.w);
    __nv_bfloat162 r2 = __floats2bfloat162_rn(b.x, b.y);
    __nv_bfloat162 r3 = __floats2bfloat162_rn(b.z, b.w);
    uint4 o;
    o.x = *(const unsigned*)&r0; o.y = *(const unsigned*)&r1;
    o.z = *(const unsigned*)&r2; o.w = *(const unsigned*)&r3;
    *(uint4*)(dst + row * (size_t)dst_stride + col_off + col) = o;
}

// ---------------- precompute xproj = W_ih1 @ emb^T + biases ----------------
__global__ void __launch_bounds__(512)
xproj_kernel(const float* __restrict__ Wih1,
             const float* __restrict__ bih1, const float* __restrict__ bhh1,
             const float* __restrict__ emb) {
    __shared__ __align__(16) float W[16 * E];
    int b   = blockIdx.x;
    int tid = threadIdx.x;
    for (int i = tid; i < 16 * E; i += 512)
        W[i] = Wih1[(size_t)b * 16 * E + i];
    __syncthreads();
    for (int o = tid; o < 16 * NV; o += 512) {
        int r = o & 15, v = o >> 4;
        const float4* ev = (const float4*)(emb + (size_t)v * E);
        const float4* wr = (const float4*)(W + r * E);
        float acc = 0.f;
        #pragma unroll 4
        for (int k = 0; k < E / 4; k++) {
            float4 a = wr[k], c = ev[k];
            acc = fmaf(a.x, c.x, acc); acc = fmaf(a.y, c.y, acc);
            acc = fmaf(a.z, c.z, acc); acc = fmaf(a.w, c.w, acc);
        }
        int row = b * 16 + r;
        g_xproj[(size_t)v * G4 + row] = acc + bih1[row] + bhh1[row];
    }
}

// ---------------- persistent controller: ONE barrier per step ----------------
__global__ void __launch_bounds__(NT, 1)
nas_persist(const int*   __restrict__ input_id,
            const float* __restrict__ bout,
            float* __restrict__ out) {
    __shared__ __align__(16) float sV[2 * HH];   // [h1(t) ; h2(t-1)]
    __shared__ float sG[48];
    __shared__ float sL[SS];
    __shared__ int   sId;

    const int tid  = threadIdx.x;
    const int w    = tid >> 5;
    const int lane = tid & 31;
    const int b    = blockIdx.x;
    const int u0   = b * UPB;

    for (int t = 0; t < TT; t++) {
        const int par = t & 1;   // read buffers = par, write buffers = par^1

        if (t == 0) {
            int id0 = *input_id;
            const float* xp = g_xproj + (size_t)id0 * G4;
            #pragma unroll
            for (int k = 0; k < 3; k++) {
                int u = tid + k * NT;
                float gi = xp[u], gg = xp[2 * HH + u], go = xp[3 * HH + u];
                float cn = fsigm(gi) * ftanh(gg);            // c_old = 0
                sV[u] = fsigm(go) * ftanh(cn);
                if (u >= u0 && u < u0 + UPB) g_c1[1][u] = cn;
                sV[HH + u] = 0.f;                             // h2(-1) = 0
            }
        } else {
            // prefetch (independent of argmax): h2(t-1), g1(t-1), c1(t-1)
            float hh[3], a0[3], a1[3], a2[3], a3[3], cc[3];
            #pragma unroll
            for (int k = 0; k < 3; k++) {
                int u = tid + k * NT;
                hh[k] = g_h2[par][u];
                a0[k] = g_g1[par][u];          a1[k] = g_g1[par][HH + u];
                a2[k] = g_g1[par][2 * HH + u]; a3[k] = g_g1[par][3 * HH + u];
                cc[k] = g_c1[par][u];
            }
            #pragma unroll
            for (int k = 0; k < 3; k++) sV[HH + tid + k * NT] = hh[k];
            __syncthreads();

            // logits(t-1): 2 bf16 head rows per warp, redundant per block
            {
                float acc[2];
                const __nv_bfloat16* base =
                    g_woutb + ((size_t)(t - 1) * SS + 2 * w) * HH;
                dotN<2, 6>(base, HH, sV + HH, lane, acc);
                acc[0] = warpsum(acc[0]);
                acc[1] = warpsum(acc[1]);
                if (lane == 0) {
                    sL[2 * w]     = acc[0] + bout[(t - 1) * SS + 2 * w];
                    sL[2 * w + 1] = acc[1] + bout[(t - 1) * SS + 2 * w + 1];
                }
            }
            __syncthreads();

            if (w == 0) {   // exact log_softmax + argmax (first-index tie-break)
                float v = sL[lane];
                float m = v;
                #pragma unroll
                for (int o = 16; o; o >>= 1) m = fmaxf(m, __shfl_xor_sync(0xffffffffu, m, o));
                float e = expf(v - m), se = e;
                #pragma unroll
                for (int o = 16; o; o >>= 1) se += __shfl_xor_sync(0xffffffffu, se, o);
                float lse = m + logf(se);
                if (b == 0) out[(t - 1) * SS + lane] = v - lse;
                float bv = v; int bi = lane;
                #pragma unroll
                for (int o = 16; o; o >>= 1) {
                    float ov = __shfl_xor_sync(0xffffffffu, bv, o);
                    int   oi = __shfl_xor_sync(0xffffffffu, bi, o);
                    if (ov > bv || (ov == bv && oi < bi)) { bv = ov; bi = oi; }
                }
                if (lane == 0) sId = ((t - 1) & 3) * SS + bi;
            }
            __syncthreads();

            // build full h1(t) redundantly; update own c1 units
            const float* xp = g_xproj + (size_t)sId * G4;
            #pragma unroll
            for (int k = 0; k < 3; k++) {
                int u = tid + k * NT;
                float gi = a0[k] + xp[u];
                float gf = a1[k] + xp[HH + u];
                float gg = a2[k] + xp[2 * HH + u];
                float go = a3[k] + xp[3 * HH + u];
                float cn = fsigm(gf) * cc[k] + fsigm(gi) * ftanh(gg);
                sV[u] = fsigm(go) * ftanh(cn);
                if (u >= u0 && u < u0 + UPB) g_c1[par ^ 1][u] = cn;
            }
        }
        __syncthreads();

        // cell2 gates: 3 consecutive concat rows (3072) per warp, one pass
        {
            int gate = w >> 2;
            int j0   = (w & 3) * 3;
            int grow = gate * HH + u0 + j0;
            float acc[3];
            dotN<3, 12>(g_w2cat + (size_t)grow * (2 * HH), 2 * HH, sV, lane, acc);
            #pragma unroll
            for (int q = 0; q < 3; q++) acc[q] = warpsum(acc[q]);
            if (lane == 0) {
                sG[gate * 12 + j0]     = acc[0] + g_b2sum[grow];
                sG[gate * 12 + j0 + 1] = acc[1] + g_b2sum[grow + 1];
                sG[gate * 12 + j0 + 2] = acc[2] + g_b2sum[grow + 2];
            }
        }
        // g1(t) = W_hh1 @ h1(t): 3 consecutive rows per warp, distributed
        {
            int row = b * 48 + w * 3;
            float acc[3];
            dotN<3, 6>(g_whh1 + (size_t)row * HH, HH, sV, lane, acc);
            #pragma unroll
            for (int q = 0; q < 3; q++) acc[q] = warpsum(acc[q]);
            if (lane == 0) {
                g_g1[par ^ 1][row]     = acc[0];
                g_g1[par ^ 1][row + 1] = acc[1];
                g_g1[par ^ 1][row + 2] = acc[2];
            }
        }
        __syncthreads();

        if (tid < UPB) {
            int u = u0 + tid;
            float gi = sG[tid], gf = sG[12 + tid], gg = sG[24 + tid], go = sG[36 + tid];
            float c  = g_c2[u];
            float cn = fsigm(gf) * c + fsigm(gi) * ftanh(gg);
            g_c2[u]          = cn;
            g_h2[par ^ 1][u] = fsigm(go) * ftanh(cn);
        }
        grid_sync(b, (unsigned)(t + 1));
    }

    // epilogue: logits(47) from h2(47) (in g_h2[0]); block 0 only
    if (b == 0) {
        #pragma unroll
        for (int k = 0; k < 3; k++) {
            int u = tid + k * NT;
            sV[HH + u] = g_h2[0][u];
        }
        __syncthreads();
        float acc[2];
        const __nv_bfloat16* base = g_woutb + ((size_t)47 * SS + 2 * w) * HH;
        dotN<2, 6>(base, HH, sV + HH, lane, acc);
        acc[0] = warpsum(acc[0]);
        acc[1] = warpsum(acc[1]);
        if (lane == 0) {
            sL[2 * w]     = acc[0] + bout[47 * SS + 2 * w];
            sL[2 * w + 1] = acc[1] + bout[47 * SS + 2 * w + 1];
        }
        __syncthreads();
        if (w == 0) {
            float v = sL[lane];
            float m = v;
            #pragma unroll
            for (int o = 16; o; o >>= 1) m = fmaxf(m, __shfl_xor_sync(0xffffffffu, m, o));
            float e = expf(v - m), se = e;
            #pragma unroll
            for (int o = 16; o; o >>= 1) se += __shfl_xor_sync(0xffffffffu, se, o);
            float lse = m + logf(se);
            out[47 * SS + lane] = v - lse;
        }
    }
}

extern "C" void kernel_launch(void* const* d_in, const int* in_sizes, int n_in,
                              void* d_out, int out_size) {
    const int*   input_id = (const int*)  d_in[0];
    const float* emb      = (const float*)d_in[1];
    const float* W_ih1    = (const float*)d_in[2];
    const float* W_hh1    = (const float*)d_in[3];
    const float* b_ih1    = (const float*)d_in[4];
    const float* b_hh1    = (const float*)d_in[5];
    const float* W_ih2    = (const float*)d_in[6];
    const float* W_hh2    = (const float*)d_in[7];
    const float* b_ih2    = (const float*)d_in[8];
    const float* b_hh2    = (const float*)d_in[9];
    const float* W_out    = (const float*)d_in[10];
    const float* b_out    = (const float*)d_in[11];
    float* out = (float*)d_out;

    __nv_bfloat16* w2cat_d; cudaGetSymbolAddress((void**)&w2cat_d, g_w2cat);
    __nv_bfloat16* whh1_d;  cudaGetSymbolAddress((void**)&whh1_d,  g_whh1);
    __nv_bfloat16* woutb_d; cudaGetSymbolAddress((void**)&woutb_d, g_woutb);

    const int cvtW = (WELEM / 8 + 255) / 256;
    const int cvtO = (WOUT_ELEMS / 8 + 255) / 256;
    init_kernel<<<1, 1024>>>(b_ih2, b_hh2);
    cvt_kernel<<<cvtW, 256>>>(W_ih2, w2cat_d, 2 * HH, 0,  WELEM);
    cvt_kernel<<<cvtW, 256>>>(W_hh2, w2cat_d, 2 * HH, HH, WELEM);
    cvt_kernel<<<cvtW, 256>>>(W_hh1, whh1_d, HH, 0, WELEM);
    cvt_kernel<<<cvtO, 256>>>(W_out, woutb_d, HH, 0, WOUT_ELEMS);
    xproj_kernel<<<G4 / 16, 512>>>(W_ih1, b_ih1, b_hh1, emb);
    nas_persist<<<NB, NT>>>(input_id, b_out, out);
}

// round 8
// speedup vs baseline: 1.2883x; 1.0135x over previous
#include <cuda_runtime.h>
#include <cuda_bf16.h>
#include <math.h>

#define E    512
#define HH   1536
#define G4   6144
#define SS   32
#define TT   48
#define NV   128
#define NB   128       // persistent blocks (1/SM)
#define NT   768       // 24 warps
#define UPB  12        // h2/c2 units per block
#define LSTR 64        // logit slot stride in floats (256B, own L2 line)
#define WELEM      (G4 * HH)
#define WOUT_ELEMS (TT * SS * HH)

// ---------------- persistent device state ----------------
__device__ float          g_xproj[NV * G4];            // W_ih1@emb[v] + b_ih1 + b_hh1
__device__ float          g_b2sum[G4];                 // b_ih2 + b_hh2
__device__ __nv_bfloat16  g_w2cat[(size_t)G4 * 2 * HH];// [W_ih2 | W_hh2] rows of 3072
__device__ __nv_bfloat16  g_whh1[WELEM];
__device__ __nv_bfloat16  g_woutb[WOUT_ELEMS];         // bf16 head
__device__ float          g_c1[2][HH];
__device__ float          g_c2[HH];
__device__ float          g_h2[2][HH];
__device__ float          g_g1[2][G4];                 // W_hh1 @ h1(t), double buffered
__device__ float          g_log3[3][SS * LSTR];        // triple-buffered padded logits
__device__ unsigned       g_flags[NB];
__device__ unsigned       g_release;

__device__ __forceinline__ float fsigm(float x) {
    return __fdividef(1.0f, 1.0f + __expf(-x));
}
__device__ __forceinline__ float ftanh(float x) {
    x = fminf(fmaxf(x, -15.0f), 15.0f);
    float e = __expf(2.0f * x);
    return __fdividef(e - 1.0f, e + 1.0f);
}
__device__ __forceinline__ float warpsum(float v) {
    #pragma unroll
    for (int o = 16; o; o >>= 1) v += __shfl_down_sync(0xffffffffu, v, o);
    return v;
}

// NR consecutive bf16 rows (stride elems), accumulate into acc[] (no init).
template<int NR, int SEGS>
__device__ __forceinline__ void dotN_acc(const __nv_bfloat16* __restrict__ base,
                                         size_t stride, const float* __restrict__ sv,
                                         int lane, float* acc) {
    #pragma unroll
    for (int j = 0; j < SEGS; j++) {
        int seg = lane + 32 * j;
        const float4* v = (const float4*)(sv + seg * 8);
        float4 v0 = v[0], v1 = v[1];
        #pragma unroll
        for (int r = 0; r < NR; r++) {
            uint4 a = __ldg((const uint4*)(base + r * stride) + seg);
            float2 p;
            p = __bfloat1622float2(*(const __nv_bfloat162*)&a.x);
            acc[r] = fmaf(p.x, v0.x, acc[r]); acc[r] = fmaf(p.y, v0.y, acc[r]);
            p = __bfloat1622float2(*(const __nv_bfloat162*)&a.y);
            acc[r] = fmaf(p.x, v0.z, acc[r]); acc[r] = fmaf(p.y, v0.w, acc[r]);
            p = __bfloat1622float2(*(const __nv_bfloat162*)&a.z);
            acc[r] = fmaf(p.x, v1.x, acc[r]); acc[r] = fmaf(p.y, v1.y, acc[r]);
            p = __bfloat1622float2(*(const __nv_bfloat162*)&a.w);
            acc[r] = fmaf(p.x, v1.z, acc[r]); acc[r] = fmaf(p.y, v1.w, acc[r]);
        }
    }
}

// contention-free grid barrier: per-block flags + single release word
__device__ __forceinline__ void grid_sync(int b, unsigned ep) {
    __threadfence();
    __syncthreads();
    if (b == 0) {
        if (threadIdx.x < NB && threadIdx.x != 0) {
            volatile unsigned* f = &g_flags[threadIdx.x];
            while (*f < ep) { __nanosleep(32); }
        }
        __syncthreads();
        if (threadIdx.x == 0) {
            __threadfence();
            *(volatile unsigned*)&g_release = ep;
        }
    } else {
        if (threadIdx.x == 0) {
            *(volatile unsigned*)&g_flags[b] = ep;
            volatile unsigned* r = &g_release;
            while (*r < ep) { __nanosleep(32); }
            __threadfence();
        }
    }
    __syncthreads();
}

// ---------------- init ----------------
__global__ void init_kernel(const float* __restrict__ b_ih2,
                            const float* __restrict__ b_hh2) {
    int tid = threadIdx.x;  // 1024
    if (tid == 0) g_release = 0u;
    if (tid < NB) g_flags[tid] = 0u;
    for (int i = tid; i < 3 * SS * LSTR; i += 1024)
        ((float*)g_log3)[i] = 0.0f;
    for (int i = tid; i < HH; i += 1024) {
        g_c2[i]    = 0.0f;
        g_h2[0][i] = 0.0f;
    }
    for (int i = tid; i < G4; i += 1024) g_b2sum[i] = b_ih2[i] + b_hh2[i];
}

// ---------------- fused fp32 -> bf16 conversions (4 jobs via blockIdx.y) ----
__global__ void __launch_bounds__(256)
cvt_all(const float* __restrict__ Wih2, const float* __restrict__ Whh2,
        const float* __restrict__ Whh1, const float* __restrict__ Wout,
        __nv_bfloat16* __restrict__ w2cat, __nv_bfloat16* __restrict__ whh1,
        __nv_bfloat16* __restrict__ woutb) {
    long i = ((long)blockIdx.x * 256 + threadIdx.x) * 8;
    int job = blockIdx.y;
    const float* src;
    __nv_bfloat16* dst;
    long nelem, stride, coloff;
    if (job == 0)      { src = Wih2; dst = w2cat; nelem = WELEM; stride = 2 * HH; coloff = 0; }
    else if (job == 1) { src = Whh2; dst = w2cat; nelem = WELEM; stride = 2 * HH; coloff = HH; }
    else if (job == 2) { src = Whh1; dst = whh1;  nelem = WELEM; stride = HH;     coloff = 0; }
    else               { src = Wout; dst = woutb; nelem = WOUT_ELEMS; stride = HH; coloff = 0; }
    if (i >= nelem) return;
    long row = i / HH, col = i % HH;
    float4 a = *(const float4*)(src + i);
    float4 b = *(const float4*)(src + i + 4);
    __nv_bfloat162 r0 = __floats2bfloat162_rn(a.x, a.y);
    __nv_bfloat162 r1 = __floats2bfloat162_rn(a.z, a.w);
    __nv_bfloat162 r2 = __floats2bfloat162_rn(b.x, b.y);
    __nv_bfloat162 r3 = __floats2bfloat162_rn(b.z, b.w);
    uint4 o;
    o.x = *(const unsigned*)&r0; o.y = *(const unsigned*)&r1;
    o.z = *(const unsigned*)&r2; o.w = *(const unsigned*)&r3;
    *(uint4*)(dst + row * stride + coloff + col) = o;
}

// ---------------- precompute xproj = W_ih1 @ emb^T + biases ----------------
__global__ void __launch_bounds__(512)
xproj_kernel(const float* __restrict__ Wih1,
             const float* __restrict__ bih1, const float* __restrict__ bhh1,
             const float* __restrict__ emb) {
    __shared__ __align__(16) float W[16 * E];
    int b   = blockIdx.x;
    int tid = threadIdx.x;
    for (int i = tid; i < 16 * E; i += 512)
        W[i] = Wih1[(size_t)b * 16 * E + i];
    __syncthreads();
    for (int o = tid; o < 16 * NV; o += 512) {
        int r = o & 15, v = o >> 4;
        const float4* ev = (const float4*)(emb + (size_t)v * E);
        const float4* wr = (const float4*)(W + r * E);
        float acc = 0.f;
        #pragma unroll 4
        for (int k = 0; k < E / 4; k++) {
            float4 a = wr[k], c = ev[k];
            acc = fmaf(a.x, c.x, acc); acc = fmaf(a.y, c.y, acc);
            acc = fmaf(a.z, c.z, acc); acc = fmaf(a.w, c.w, acc);
        }
        int row = b * 16 + r;
        g_xproj[(size_t)v * G4 + row] = acc + bih1[row] + bhh1[row];
    }
}

// ---------------- persistent controller ----------------
__global__ void __launch_bounds__(NT, 1)
nas_persist(const int*   __restrict__ input_id,
            const float* __restrict__ bout,
            float* __restrict__ out) {
    __shared__ __align__(16) float sV[2 * HH];   // [h1(t) ; h2(t-1)]
    __shared__ float sWo[SS * UPB];
    __shared__ float sG[48];

    const int tid  = threadIdx.x;
    const int w    = tid >> 5;
    const int lane = tid & 31;
    const int b    = blockIdx.x;
    const int u0   = b * UPB;

    // this warp's rows: cell2 local rows l0=2w, l0+1 (l = gate*12 + j)
    const int l0   = 2 * w;
    const int gate = l0 / 12;
    const int j0   = l0 % 12;
    const int grow = gate * HH + u0 + j0;
    const __nv_bfloat16* w2base = g_w2cat + (size_t)grow * (2 * HH);
    const int r1row = b * 48 + l0;

    for (int t = 0; t < TT; t++) {
        const int par = t & 1;
        const int rb = t % 3, wb = (t + 1) % 3, zb = (t + 2) % 3;

        // ---- loads (all argmax-independent) ----
        float lg = 0.f;
        if (t > 0) lg = g_log3[rb][lane * LSTR] + bout[(t - 1) * SS + lane];
        float h2r[2], a0[2], a1[2], a2[2], a3[2], cc[2];
        #pragma unroll
        for (int k = 0; k < 2; k++) {
            int u = tid + k * NT;
            h2r[k] = g_h2[par][u];
            if (t > 0) {
                a0[k] = g_g1[par][u];          a1[k] = g_g1[par][HH + u];
                a2[k] = g_g1[par][2 * HH + u]; a3[k] = g_g1[par][3 * HH + u];
                cc[k] = g_c1[par][u];
            }
        }
        if (tid < SS * UPB) {   // Wout[t] slice for this block's units
            int s = tid / UPB, j = tid % UPB;
            sWo[tid] = __bfloat162float(g_woutb[((size_t)t * SS + s) * HH + u0 + j]);
        }

        // ---- per-warp redundant softmax/argmax of step t-1 ----
        int sid = 0;
        if (t > 0) {
            float v = lg;
            float m = v;
            #pragma unroll
            for (int o = 16; o; o >>= 1) m = fmaxf(m, __shfl_xor_sync(0xffffffffu, m, o));
            float e = expf(v - m), se = e;
            #pragma unroll
            for (int o = 16; o; o >>= 1) se += __shfl_xor_sync(0xffffffffu, se, o);
            float lse = m + logf(se);
            if (b == 0 && w == 0) out[(t - 1) * SS + lane] = v - lse;
            float bv = v; int bi = lane;
            #pragma unroll
            for (int o = 16; o; o >>= 1) {
                float ov = __shfl_xor_sync(0xffffffffu, bv, o);
                int   oi = __shfl_xor_sync(0xffffffffu, bi, o);
                if (ov > bv || (ov == bv && oi < bi)) { bv = ov; bi = oi; }
            }
            sid = ((t - 1) & 3) * SS + bi;   // uniform across warp
        }

        // ---- stage h2(t-1) ----
        #pragma unroll
        for (int k = 0; k < 2; k++) sV[HH + tid + k * NT] = h2r[k];
        __syncthreads();

        // ---- dotA: W_hh2 @ h2(t-1) (argmax-independent) ----
        float acc[2] = {0.f, 0.f};
        dotN_acc<2, 6>(w2base + HH, 2 * HH, sV + HH, lane, acc);

        // ---- build h1(t) redundantly; own c1 slice ----
        if (t == 0) {
            int id0 = *input_id;
            const float* xp = g_xproj + (size_t)id0 * G4;
            #pragma unroll
            for (int k = 0; k < 2; k++) {
                int u = tid + k * NT;
                float gi = xp[u], gg = xp[2 * HH + u], go = xp[3 * HH + u];
                float cn = fsigm(gi) * ftanh(gg);
                sV[u] = fsigm(go) * ftanh(cn);
                if (u >= u0 && u < u0 + UPB) g_c1[1][u] = cn;
            }
        } else {
            const float* xp = g_xproj + (size_t)sid * G4;
            #pragma unroll
            for (int k = 0; k < 2; k++) {
                int u = tid + k * NT;
                float gi = a0[k] + xp[u];
                float gf = a1[k] + xp[HH + u];
                float gg = a2[k] + xp[2 * HH + u];
                float go = a3[k] + xp[3 * HH + u];
                float cn = fsigm(gf) * cc[k] + fsigm(gi) * ftanh(gg);
                sV[u] = fsigm(go) * ftanh(cn);
                if (u >= u0 && u < u0 + UPB) g_c1[par ^ 1][u] = cn;
            }
        }
        __syncthreads();

        // ---- dotB: + W_ih2 @ h1(t); W_hh1 @ h1(t) ----
        dotN_acc<2, 6>(w2base, 2 * HH, sV, lane, acc);
        acc[0] = warpsum(acc[0]);
        acc[1] = warpsum(acc[1]);
        if (lane == 0) {
            sG[l0]     = acc[0] + g_b2sum[grow];
            sG[l0 + 1] = acc[1] + g_b2sum[grow + 1];
        }
        {
            float r[2] = {0.f, 0.f};
            dotN_acc<2, 6>(g_whh1 + (size_t)r1row * HH, HH, sV, lane, r);
            r[0] = warpsum(r[0]);
            r[1] = warpsum(r[1]);
            if (lane == 0) {
                g_g1[par ^ 1][r1row]     = r[0];
                g_g1[par ^ 1][r1row + 1] = r[1];
            }
        }
        __syncthreads();

        // ---- finalize own h2 units + partial logits -> atomics ----
        if (w == 0) {
            float hn = 0.f;
            if (lane < UPB) {
                int u = u0 + lane;
                float gi = sG[lane], gf = sG[12 + lane], gg = sG[24 + lane], go = sG[36 + lane];
                float c  = g_c2[u];
                float cn = fsigm(gf) * c + fsigm(gi) * ftanh(gg);
                g_c2[u]          = cn;
                hn               = fsigm(go) * ftanh(cn);
                g_h2[par ^ 1][u] = hn;
            }
            float p = 0.f;
            #pragma unroll
            for (int j = 0; j < UPB; j++) {
                float hj = __shfl_sync(0xffffffffu, hn, j);
                p = fmaf(sWo[lane * UPB + j], hj, p);
            }
            atomicAdd(&g_log3[wb][lane * LSTR], p);
        }
        if (b == 0 && w == 1) g_log3[zb][lane * LSTR] = 0.0f;  // recycle buffer

        grid_sync(b, (unsigned)(t + 1));
    }

    // epilogue: logp(47) from g_log3[48%3 = 0]
    if (b == 0 && w == 0) {
        float v = g_log3[0][lane * LSTR] + bout[47 * SS + lane];
        float m = v;
        #pragma unroll
        for (int o = 16; o; o >>= 1) m = fmaxf(m, __shfl_xor_sync(0xffffffffu, m, o));
        float e = expf(v - m), se = e;
        #pragma unroll
        for (int o = 16; o; o >>= 1) se += __shfl_xor_sync(0xffffffffu, se, o);
        float lse = m + logf(se);
        out[47 * SS + lane] = v - lse;
    }
}

extern "C" void kernel_launch(void* const* d_in, const int* in_sizes, int n_in,
                              void* d_out, int out_size) {
    const int*   input_id = (const int*)  d_in[0];
    const float* emb      = (const float*)d_in[1];
    const float* W_ih1    = (const float*)d_in[2];
    const float* W_hh1    = (const float*)d_in[3];
    const float* b_ih1    = (const float*)d_in[4];
    const float* b_hh1    = (const float*)d_in[5];
    const float* W_ih2    = (const float*)d_in[6];
    const float* W_hh2    = (const float*)d_in[7];
    const float* b_ih2    = (const float*)d_in[8];
    const float* b_hh2    = (const float*)d_in[9];
    const float* W_out    = (const float*)d_in[10];
    const float* b_out    = (const float*)d_in[11];
    float* out = (float*)d_out;

    __nv_bfloat16* w2cat_d; cudaGetSymbolAddress((void**)&w2cat_d, g_w2cat);
    __nv_bfloat16* whh1_d;  cudaGetSymbolAddress((void**)&whh1_d,  g_whh1);
    __nv_bfloat16* woutb_d; cudaGetSymbolAddress((void**)&woutb_d, g_woutb);

    dim3 cvt_grid((WELEM / 8 + 255) / 256, 4);
    init_kernel<<<1, 1024>>>(b_ih2, b_hh2);
    cvt_all<<<cvt_grid, 256>>>(W_ih2, W_hh2, W_hh1, W_out, w2cat_d, whh1_d, woutb_d);
    xproj_kernel<<<G4 / 16, 512>>>(W_ih1, b_ih1, b_hh1, emb);
    nas_persist<<<NB, NT>>>(input_id, b_out, out);
}

// round 9
// speedup vs baseline: 1.6592x; 1.2879x over previous
#include <cuda_runtime.h>
#include <cuda_bf16.h>
#include <math.h>

#define E    512
#define HH   1536
#define G4   6144
#define SS   32
#define TT   48
#define NV   128
#define NB   128       // persistent blocks (1/SM)
#define NT   768       // 24 warps
#define UPB  12        // h2/c2 units per block
#define LSTR 64        // logit slot stride in floats (256B, own L2 line)
#define WELEM      (G4 * HH)
#define WOUT_ELEMS (TT * SS * HH)

// ---------------- persistent device state ----------------
__device__ float          g_xproj[NV * G4];            // W_ih1@emb[v] + b_ih1 + b_hh1
__device__ float          g_b2sum[G4];                 // b_ih2 + b_hh2
__device__ __nv_bfloat16  g_w2cat[(size_t)G4 * 2 * HH];// [W_ih2 | W_hh2] rows of 3072
__device__ __nv_bfloat16  g_whh1[WELEM];
__device__ __nv_bfloat16  g_woutb[WOUT_ELEMS];         // bf16 head
__device__ float          g_c1[2][HH];
__device__ float          g_c2[HH];
__device__ float          g_h2[2][HH];
__device__ float          g_g1[2][G4];                 // W_hh1 @ h1(t), double buffered
__device__ float          g_log3[3][SS * LSTR];        // triple-buffered padded logits
__device__ unsigned       g_flags[NB];
__device__ unsigned       g_release;

__device__ __forceinline__ float fsigm(float x) {
    return __fdividef(1.0f, 1.0f + __expf(-x));
}
__device__ __forceinline__ float ftanh(float x) {
    x = fminf(fmaxf(x, -15.0f), 15.0f);
    float e = __expf(2.0f * x);
    return __fdividef(e - 1.0f, e + 1.0f);
}
__device__ __forceinline__ float warpsum(float v) {
    #pragma unroll
    for (int o = 16; o; o >>= 1) v += __shfl_down_sync(0xffffffffu, v, o);
    return v;
}

// NR consecutive bf16 rows (stride elems), accumulate into acc[] (no init).
template<int NR, int SEGS>
__device__ __forceinline__ void dotN_acc(const __nv_bfloat16* __restrict__ base,
                                         size_t stride, const float* __restrict__ sv,
                                         int lane, float* acc) {
    #pragma unroll
    for (int j = 0; j < SEGS; j++) {
        int seg = lane + 32 * j;
        const float4* v = (const float4*)(sv + seg * 8);
        float4 v0 = v[0], v1 = v[1];
        #pragma unroll
        for (int r = 0; r < NR; r++) {
            uint4 a = __ldg((const uint4*)(base + r * stride) + seg);
            float2 p;
            p = __bfloat1622float2(*(const __nv_bfloat162*)&a.x);
            acc[r] = fmaf(p.x, v0.x, acc[r]); acc[r] = fmaf(p.y, v0.y, acc[r]);
            p = __bfloat1622float2(*(const __nv_bfloat162*)&a.y);
            acc[r] = fmaf(p.x, v0.z, acc[r]); acc[r] = fmaf(p.y, v0.w, acc[r]);
            p = __bfloat1622float2(*(const __nv_bfloat162*)&a.z);
            acc[r] = fmaf(p.x, v1.x, acc[r]); acc[r] = fmaf(p.y, v1.y, acc[r]);
            p = __bfloat1622float2(*(const __nv_bfloat162*)&a.w);
            acc[r] = fmaf(p.x, v1.z, acc[r]); acc[r] = fmaf(p.y, v1.w, acc[r]);
        }
    }
}

// contention-free grid barrier: per-block flags + single release word
__device__ __forceinline__ void grid_sync(int b, unsigned ep) {
    __threadfence();
    __syncthreads();
    if (b == 0) {
        if (threadIdx.x < NB && threadIdx.x != 0) {
            volatile unsigned* f = &g_flags[threadIdx.x];
            while (*f < ep) { __nanosleep(32); }
        }
        __syncthreads();
        if (threadIdx.x == 0) {
            __threadfence();
            *(volatile unsigned*)&g_release = ep;
        }
    } else {
        if (threadIdx.x == 0) {
            *(volatile unsigned*)&g_flags[b] = ep;
            volatile unsigned* r = &g_release;
            while (*r < ep) { __nanosleep(32); }
            __threadfence();
        }
    }
    __syncthreads();
}

// ---------------- init ----------------
__global__ void init_kernel(const float* __restrict__ b_ih2,
                            const float* __restrict__ b_hh2) {
    int tid = threadIdx.x;  // 1024
    if (tid == 0) g_release = 0u;
    if (tid < NB) g_flags[tid] = 0u;
    for (int i = tid; i < 3 * SS * LSTR; i += 1024)
        ((float*)g_log3)[i] = 0.0f;
    for (int i = tid; i < HH; i += 1024) {
        g_c2[i]    = 0.0f;
        g_h2[0][i] = 0.0f;
    }
    for (int i = tid; i < G4; i += 1024) g_b2sum[i] = b_ih2[i] + b_hh2[i];
}

// ---------------- fused fp32 -> bf16 conversions (4 jobs via blockIdx.y) ----
__global__ void __launch_bounds__(256)
cvt_all(const float* __restrict__ Wih2, const float* __restrict__ Whh2,
        const float* __restrict__ Whh1, const float* __restrict__ Wout,
        __nv_bfloat16* __restrict__ w2cat, __nv_bfloat16* __restrict__ whh1,
        __nv_bfloat16* __restrict__ woutb) {
    long i = ((long)blockIdx.x * 256 + threadIdx.x) * 8;
    int job = blockIdx.y;
    const float* src;
    __nv_bfloat16* dst;
    long nelem, stride, coloff;
    if (job == 0)      { src = Wih2; dst = w2cat; nelem = WELEM; stride = 2 * HH; coloff = 0; }
    else if (job == 1) { src = Whh2; dst = w2cat; nelem = WELEM; stride = 2 * HH; coloff = HH; }
    else if (job == 2) { src = Whh1; dst = whh1;  nelem = WELEM; stride = HH;     coloff = 0; }
    else               { src = Wout; dst = woutb; nelem = WOUT_ELEMS; stride = HH; coloff = 0; }
    if (i >= nelem) return;
    long row = i / HH, col = i % HH;
    float4 a = *(const float4*)(src + i);
    float4 b = *(const float4*)(src + i + 4);
    __nv_bfloat162 r0 = __floats2bfloat162_rn(a.x, a.y);
    __nv_bfloat162 r1 = __floats2bfloat162_rn(a.z, a.w);
    __nv_bfloat162 r2 = __floats2bfloat162_rn(b.x, b.y);
    __nv_bfloat162 r3 = __floats2bfloat162_rn(b.z, b.w);
    uint4 o;
    o.x = *(const unsigned*)&r0; o.y = *(const unsigned*)&r1;
    o.z = *(const unsigned*)&r2; o.w = *(const unsigned*)&r3;
    *(uint4*)(dst + row * stride + coloff + col) = o;
}

// ---------------- xproj = W_ih1 @ emb^T + biases (register-tiled GEMM) ------
// 384 blocks x 512 threads. Warp w owns W row r = b*16 + w IN REGISTERS.
// emb staged through smem in 16-row chunks; W_ih1 read exactly once from DRAM.
#define XPV 16   // emb rows per chunk
__global__ void __launch_bounds__(512)
xproj_kernel(const float* __restrict__ Wih1,
             const float* __restrict__ bih1, const float* __restrict__ bhh1,
             const float* __restrict__ emb) {
    __shared__ __align__(16) float sE[XPV][E + 8];   // padded rows, 33 KB
    const int tid  = threadIdx.x;
    const int w    = tid >> 5;
    const int lane = tid & 31;
    const int b    = blockIdx.x;
    const int r    = b * 16 + w;                     // global W_ih1 row

    float4 W4[4];                                    // W[r][lane*16 .. +15]
    const float4* wr = (const float4*)(Wih1 + (size_t)r * E);
    #pragma unroll
    for (int i = 0; i < 4; i++) W4[i] = __ldg(&wr[lane * 4 + i]);
    const float bsum = __ldg(&bih1[r]) + __ldg(&bhh1[r]);

    for (int c = 0; c < NV / XPV; c++) {
        __syncthreads();   // previous chunk fully consumed
        // cooperative load: XPV rows x 128 float4
        for (int idx = tid; idx < XPV * (E / 4); idx += 512) {
            int v  = idx >> 7;          // /128
            int e4 = idx & 127;
            float4 d = __ldg((const float4*)(emb + (size_t)(c * XPV + v) * E) + e4);
            *(float4*)&sE[v][e4 * 4] = d;
        }
        __syncthreads();

        #pragma unroll 4
        for (int v = 0; v < XPV; v++) {
            const float* ev = &sE[v][lane * 16];
            float acc = 0.f;
            #pragma unroll
            for (int i = 0; i < 4; i++) {
                float4 x = *(const float4*)(ev + 4 * i);
                acc = fmaf(W4[i].x, x.x, acc);
                acc = fmaf(W4[i].y, x.y, acc);
                acc = fmaf(W4[i].z, x.z, acc);
                acc = fmaf(W4[i].w, x.w, acc);
            }
            acc = warpsum(acc);
            if (lane == 0)
                g_xproj[(size_t)(c * XPV + v) * G4 + r] = acc + bsum;
        }
    }
}

// ---------------- persistent controller ----------------
__global__ void __launch_bounds__(NT, 1)
nas_persist(const int*   __restrict__ input_id,
            const float* __restrict__ bout,
            float* __restrict__ out) {
    __shared__ __align__(16) float sV[2 * HH];   // [h1(t) ; h2(t-1)]
    __shared__ float sWo[SS * UPB];
    __shared__ float sG[48];

    const int tid  = threadIdx.x;
    const int w    = tid >> 5;
    const int lane = tid & 31;
    const int b    = blockIdx.x;
    const int u0   = b * UPB;

    const int l0   = 2 * w;
    const int gate = l0 / 12;
    const int j0   = l0 % 12;
    const int grow = gate * HH + u0 + j0;
    const __nv_bfloat16* w2base = g_w2cat + (size_t)grow * (2 * HH);
    const int r1row = b * 48 + l0;

    for (int t = 0; t < TT; t++) {
        const int par = t & 1;
        const int rb = t % 3, wb = (t + 1) % 3, zb = (t + 2) % 3;

        // ---- loads (all argmax-independent) ----
        float lg = 0.f;
        if (t > 0) lg = g_log3[rb][lane * LSTR] + bout[(t - 1) * SS + lane];
        float h2r[2], a0[2], a1[2], a2[2], a3[2], cc[2];
        #pragma unroll
        for (int k = 0; k < 2; k++) {
            int u = tid + k * NT;
            h2r[k] = g_h2[par][u];
            if (t > 0) {
                a0[k] = g_g1[par][u];          a1[k] = g_g1[par][HH + u];
                a2[k] = g_g1[par][2 * HH + u]; a3[k] = g_g1[par][3 * HH + u];
                cc[k] = g_c1[par][u];
            }
        }
        if (tid < SS * UPB) {   // Wout[t] slice for this block's units
            int s = tid / UPB, j = tid % UPB;
            sWo[tid] = __bfloat162float(g_woutb[((size_t)t * SS + s) * HH + u0 + j]);
        }

        // ---- per-warp redundant softmax/argmax of step t-1 ----
        int sid = 0;
        if (t > 0) {
            float v = lg;
            float m = v;
            #pragma unroll
            for (int o = 16; o; o >>= 1) m = fmaxf(m, __shfl_xor_sync(0xffffffffu, m, o));
            float e = expf(v - m), se = e;
            #pragma unroll
            for (int o = 16; o; o >>= 1) se += __shfl_xor_sync(0xffffffffu, se, o);
            float lse = m + logf(se);
            if (b == 0 && w == 0) out[(t - 1) * SS + lane] = v - lse;
            float bv = v; int bi = lane;
            #pragma unroll
            for (int o = 16; o; o >>= 1) {
                float ov = __shfl_xor_sync(0xffffffffu, bv, o);
                int   oi = __shfl_xor_sync(0xffffffffu, bi, o);
                if (ov > bv || (ov == bv && oi < bi)) { bv = ov; bi = oi; }
            }
            sid = ((t - 1) & 3) * SS + bi;   // uniform across warp
        }

        // ---- stage h2(t-1) ----
        #pragma unroll
        for (int k = 0; k < 2; k++) sV[HH + tid + k * NT] = h2r[k];
        __syncthreads();

        // ---- dotA: W_hh2 @ h2(t-1) (argmax-independent) ----
        float acc[2] = {0.f, 0.f};
        dotN_acc<2, 6>(w2base + HH, 2 * HH, sV + HH, lane, acc);

        // ---- build h1(t) redundantly; own c1 slice ----
        if (t == 0) {
            int id0 = *input_id;
            const float* xp = g_xproj + (size_t)id0 * G4;
            #pragma unroll
            for (int k = 0; k < 2; k++) {
                int u = tid + k * NT;
                float gi = xp[u], gg = xp[2 * HH + u], go = xp[3 * HH + u];
                float cn = fsigm(gi) * ftanh(gg);
                sV[u] = fsigm(go) * ftanh(cn);
                if (u >= u0 && u < u0 + UPB) g_c1[1][u] = cn;
            }
        } else {
            const float* xp = g_xproj + (size_t)sid * G4;
            #pragma unroll
            for (int k = 0; k < 2; k++) {
                int u = tid + k * NT;
                float gi = a0[k] + xp[u];
                float gf = a1[k] + xp[HH + u];
                float gg = a2[k] + xp[2 * HH + u];
                float go = a3[k] + xp[3 * HH + u];
                float cn = fsigm(gf) * cc[k] + fsigm(gi) * ftanh(gg);
                sV[u] = fsigm(go) * ftanh(cn);
                if (u >= u0 && u < u0 + UPB) g_c1[par ^ 1][u] = cn;
            }
        }
        __syncthreads();

        // ---- dotB: + W_ih2 @ h1(t); W_hh1 @ h1(t) ----
        dotN_acc<2, 6>(w2base, 2 * HH, sV, lane, acc);
        acc[0] = warpsum(acc[0]);
        acc[1] = warpsum(acc[1]);
        if (lane == 0) {
            sG[l0]     = acc[0] + g_b2sum[grow];
            sG[l0 + 1] = acc[1] + g_b2sum[grow + 1];
        }
        {
            float r[2] = {0.f, 0.f};
            dotN_acc<2, 6>(g_whh1 + (size_t)r1row * HH, HH, sV, lane, r);
            r[0] = warpsum(r[0]);
            r[1] = warpsum(r[1]);
            if (lane == 0) {
                g_g1[par ^ 1][r1row]     = r[0];
                g_g1[par ^ 1][r1row + 1] = r[1];
            }
        }
        __syncthreads();

        // ---- finalize own h2 units + partial logits -> spread atomics ----
        if (w == 0) {
            float hn = 0.f;
            if (lane < UPB) {
                int u = u0 + lane;
                float gi = sG[lane], gf = sG[12 + lane], gg = sG[24 + lane], go = sG[36 + lane];
                float c  = g_c2[u];
                float cn = fsigm(gf) * c + fsigm(gi) * ftanh(gg);
                g_c2[u]          = cn;
                hn               = fsigm(go) * ftanh(cn);
                g_h2[par ^ 1][u] = hn;
            }
            float p = 0.f;
            #pragma unroll
            for (int j = 0; j < UPB; j++) {
                float hj = __shfl_sync(0xffffffffu, hn, j);
                p = fmaf(sWo[lane * UPB + j], hj, p);
            }
            atomicAdd(&g_log3[wb][lane * LSTR], p);
        }
        if (b == 0 && w == 1) g_log3[zb][lane * LSTR] = 0.0f;  // recycle buffer

        grid_sync(b, (unsigned)(t + 1));
    }

    // epilogue: logp(47) from g_log3[48%3 = 0]
    if (b == 0 && w == 0) {
        float v = g_log3[0][lane * LSTR] + bout[47 * SS + lane];
        float m = v;
        #pragma unroll
        for (int o = 16; o; o >>= 1) m = fmaxf(m, __shfl_xor_sync(0xffffffffu, m, o));
        float e = expf(v - m), se = e;
        #pragma unroll
        for (int o = 16; o; o >>= 1) se += __shfl_xor_sync(0xffffffffu, se, o);
        float lse = m + logf(se);
        out[47 * SS + lane] = v - lse;
    }
}

extern "C" void kernel_launch(void* const* d_in, const int* in_sizes, int n_in,
                              void* d_out, int out_size) {
    const int*   input_id = (const int*)  d_in[0];
    const float* emb      = (const float*)d_in[1];
    const float* W_ih1    = (const float*)d_in[2];
    const float* W_hh1    = (const float*)d_in[3];
    const float* b_ih1    = (const float*)d_in[4];
    const float* b_hh1    = (const float*)d_in[5];
    const float* W_ih2    = (const float*)d_in[6];
    const float* W_hh2    = (const float*)d_in[7];
    const float* b_ih2    = (const float*)d_in[8];
    const float* b_hh2    = (const float*)d_in[9];
    const float* W_out    = (const float*)d_in[10];
    const float* b_out    = (const float*)d_in[11];
    float* out = (float*)d_out;

    __nv_bfloat16* w2cat_d; cudaGetSymbolAddress((void**)&w2cat_d, g_w2cat);
    __nv_bfloat16* whh1_d;  cudaGetSymbolAddress((void**)&whh1_d,  g_whh1);
    __nv_bfloat16* woutb_d; cudaGetSymbolAddress((void**)&woutb_d, g_woutb);

    dim3 cvt_grid((WELEM / 8 + 255) / 256, 4);
    init_kernel<<<1, 1024>>>(b_ih2, b_hh2);
    cvt_all<<<cvt_grid, 256>>>(W_ih2, W_hh2, W_hh1, W_out, w2cat_d, whh1_d, woutb_d);
    xproj_kernel<<<G4 / 16, 512>>>(W_ih1, b_ih1, b_hh1, emb);
    nas_persist<<<NB, NT>>>(input_id, b_out, out);
}

// round 10
// speedup vs baseline: 1.7541x; 1.0572x over previous
#include <cuda_runtime.h>
#include <cuda_bf16.h>
#include <math.h>

#define E    512
#define HH   1536
#define G4   6144
#define SS   32
#define TT   48
#define NV   128
#define NB   128       // persistent blocks (1/SM)
#define NT   768       // 24 warps
#define UPB  12        // h2/c2 units per block
#define LSTR 64        // logit slot stride in floats (256B, own L2 line)
#define WELEM      (G4 * HH)

// ---------------- persistent device state ----------------
__device__ float          g_xproj[NV * G4];            // W_ih1@emb[v] + b_ih1 + b_hh1
__device__ float          g_b2sum[G4];                 // b_ih2 + b_hh2
__device__ __nv_bfloat16  g_w2cat[(size_t)G4 * 2 * HH];// [W_ih2 | W_hh2] rows of 3072
__device__ __nv_bfloat16  g_whh1[WELEM];
__device__ float          g_c1[2][HH];
__device__ float          g_c2[HH];
__device__ float          g_h2[2][HH];
__device__ float          g_g1[2][G4];                 // W_hh1 @ h1(t), double buffered
__device__ float          g_log3[3][SS * LSTR];        // triple-buffered padded logits
__device__ unsigned       g_flags[NB];
__device__ unsigned       g_release;

__device__ __forceinline__ float fsigm(float x) {
    return __fdividef(1.0f, 1.0f + __expf(-x));
}
__device__ __forceinline__ float ftanh(float x) {
    x = fminf(fmaxf(x, -15.0f), 15.0f);
    float e = __expf(2.0f * x);
    return __fdividef(e - 1.0f, e + 1.0f);
}
__device__ __forceinline__ float warpsum(float v) {
    #pragma unroll
    for (int o = 16; o; o >>= 1) v += __shfl_down_sync(0xffffffffu, v, o);
    return v;
}

// 2 rows from one base, vector from smem; accumulate (no init)
template<int SEGS>
__device__ __forceinline__ void dot2_acc(const __nv_bfloat16* __restrict__ base,
                                         size_t stride, const float* __restrict__ sv,
                                         int lane, float* acc) {
    #pragma unroll
    for (int j = 0; j < SEGS; j++) {
        int seg = lane + 32 * j;
        const float4* v = (const float4*)(sv + seg * 8);
        float4 v0 = v[0], v1 = v[1];
        #pragma unroll
        for (int r = 0; r < 2; r++) {
            uint4 a = __ldg((const uint4*)(base + r * stride) + seg);
            float2 p;
            p = __bfloat1622float2(*(const __nv_bfloat162*)&a.x);
            acc[r] = fmaf(p.x, v0.x, acc[r]); acc[r] = fmaf(p.y, v0.y, acc[r]);
            p = __bfloat1622float2(*(const __nv_bfloat162*)&a.y);
            acc[r] = fmaf(p.x, v0.z, acc[r]); acc[r] = fmaf(p.y, v0.w, acc[r]);
            p = __bfloat1622float2(*(const __nv_bfloat162*)&a.z);
            acc[r] = fmaf(p.x, v1.x, acc[r]); acc[r] = fmaf(p.y, v1.y, acc[r]);
            p = __bfloat1622float2(*(const __nv_bfloat162*)&a.w);
            acc[r] = fmaf(p.x, v1.z, acc[r]); acc[r] = fmaf(p.y, v1.w, acc[r]);
        }
    }
}

// FUSED: 2 rows from baseA (strideA) + 2 rows from baseB (strideB), ONE vector pass
template<int SEGS>
__device__ __forceinline__ void dot2x2_acc(const __nv_bfloat16* __restrict__ baseA,
                                           size_t strideA,
                                           const __nv_bfloat16* __restrict__ baseB,
                                           size_t strideB,
                                           const float* __restrict__ sv, int lane,
                                           float* accA, float* accB) {
    #pragma unroll
    for (int j = 0; j < SEGS; j++) {
        int seg = lane + 32 * j;
        const float4* v = (const float4*)(sv + seg * 8);
        float4 v0 = v[0], v1 = v[1];
        uint4 a0 = __ldg((const uint4*)(baseA) + seg);
        uint4 a1 = __ldg((const uint4*)(baseA + strideA) + seg);
        uint4 b0 = __ldg((const uint4*)(baseB) + seg);
        uint4 b1 = __ldg((const uint4*)(baseB + strideB) + seg);
        float2 p;
        #define ACC8(acc, q) \
            p = __bfloat1622float2(*(const __nv_bfloat162*)&q.x); \
            acc = fmaf(p.x, v0.x, acc); acc = fmaf(p.y, v0.y, acc); \
            p = __bfloat1622float2(*(const __nv_bfloat162*)&q.y); \
            acc = fmaf(p.x, v0.z, acc); acc = fmaf(p.y, v0.w, acc); \
            p = __bfloat1622float2(*(const __nv_bfloat162*)&q.z); \
            acc = fmaf(p.x, v1.x, acc); acc = fmaf(p.y, v1.y, acc); \
            p = __bfloat1622float2(*(const __nv_bfloat162*)&q.w); \
            acc = fmaf(p.x, v1.z, acc); acc = fmaf(p.y, v1.w, acc);
        ACC8(accA[0], a0)
        ACC8(accA[1], a1)
        ACC8(accB[0], b0)
        ACC8(accB[1], b1)
        #undef ACC8
    }
}

// contention-free grid barrier: per-block flags + single release word
__device__ __forceinline__ void grid_sync(int b, unsigned ep) {
    __threadfence();
    __syncthreads();
    if (b == 0) {
        if (threadIdx.x < NB && threadIdx.x != 0) {
            volatile unsigned* f = &g_flags[threadIdx.x];
            while (*f < ep) { __nanosleep(32); }
        }
        __syncthreads();
        if (threadIdx.x == 0) {
            __threadfence();
            *(volatile unsigned*)&g_release = ep;
        }
    } else {
        if (threadIdx.x == 0) {
            *(volatile unsigned*)&g_flags[b] = ep;
            volatile unsigned* r = &g_release;
            while (*r < ep) { __nanosleep(32); }
            __threadfence();
        }
    }
    __syncthreads();
}

// ---------------- init ----------------
__global__ void init_kernel(const float* __restrict__ b_ih2,
                            const float* __restrict__ b_hh2) {
    int tid = threadIdx.x;  // 1024
    if (tid == 0) g_release = 0u;
    if (tid < NB) g_flags[tid] = 0u;
    for (int i = tid; i < 3 * SS * LSTR; i += 1024)
        ((float*)g_log3)[i] = 0.0f;
    for (int i = tid; i < HH; i += 1024) {
        g_c2[i]    = 0.0f;
        g_h2[0][i] = 0.0f;
    }
    for (int i = tid; i < G4; i += 1024) g_b2sum[i] = b_ih2[i] + b_hh2[i];
}

// ------- fused preamble: 3 bf16 conversions + register-tiled xproj GEMM -----
#define XPV 16
__global__ void __launch_bounds__(512)
prep_kernel(const float* __restrict__ Wih2, const float* __restrict__ Whh2,
            const float* __restrict__ Whh1,
            __nv_bfloat16* __restrict__ w2cat, __nv_bfloat16* __restrict__ whh1,
            const float* __restrict__ Wih1,
            const float* __restrict__ bih1, const float* __restrict__ bhh1,
            const float* __restrict__ emb) {
    __shared__ __align__(16) float sE[XPV][E + 8];
    const int job = blockIdx.y;
    const int tid = threadIdx.x;

    if (job < 3) {   // bf16 conversion jobs
        long i = ((long)blockIdx.x * 512 + tid) * 8;
        if (i >= WELEM) return;
        const float* src = (job == 0) ? Wih2 : (job == 1) ? Whh2 : Whh1;
        __nv_bfloat16* dst = (job == 2) ? whh1 : w2cat;
        long stride = (job == 2) ? HH : 2 * HH;
        long coloff = (job == 1) ? HH : 0;
        long row = i / HH, col = i % HH;
        float4 a = *(const float4*)(src + i);
        float4 b = *(const float4*)(src + i + 4);
        __nv_bfloat162 r0 = __floats2bfloat162_rn(a.x, a.y);
        __nv_bfloat162 r1 = __floats2bfloat162_rn(a.z, a.w);
        __nv_bfloat162 r2 = __floats2bfloat162_rn(b.x, b.y);
        __nv_bfloat162 r3 = __floats2bfloat162_rn(b.z, b.w);
        uint4 o;
        o.x = *(const unsigned*)&r0; o.y = *(const unsigned*)&r1;
        o.z = *(const unsigned*)&r2; o.w = *(const unsigned*)&r3;
        *(uint4*)(dst + row * stride + coloff + col) = o;
        return;
    }

    // job == 3: xproj (384 blocks active)
    if (blockIdx.x >= G4 / 16) return;
    const int w    = tid >> 5;
    const int lane = tid & 31;
    const int b    = blockIdx.x;
    const int r    = b * 16 + w;

    float4 W4[4];
    const float4* wr = (const float4*)(Wih1 + (size_t)r * E);
    #pragma unroll
    for (int i = 0; i < 4; i++) W4[i] = __ldg(&wr[lane * 4 + i]);
    const float bsum = __ldg(&bih1[r]) + __ldg(&bhh1[r]);

    for (int c = 0; c < NV / XPV; c++) {
        __syncthreads();
        for (int idx = tid; idx < XPV * (E / 4); idx += 512) {
            int v  = idx >> 7;
            int e4 = idx & 127;
            float4 d = __ldg((const float4*)(emb + (size_t)(c * XPV + v) * E) + e4);
            *(float4*)&sE[v][e4 * 4] = d;
        }
        __syncthreads();
        #pragma unroll 4
        for (int v = 0; v < XPV; v++) {
            const float* ev = &sE[v][lane * 16];
            float acc = 0.f;
            #pragma unroll
            for (int i = 0; i < 4; i++) {
                float4 x = *(const float4*)(ev + 4 * i);
                acc = fmaf(W4[i].x, x.x, acc);
                acc = fmaf(W4[i].y, x.y, acc);
                acc = fmaf(W4[i].z, x.z, acc);
                acc = fmaf(W4[i].w, x.w, acc);
            }
            acc = warpsum(acc);
            if (lane == 0)
                g_xproj[(size_t)(c * XPV + v) * G4 + r] = acc + bsum;
        }
    }
}

// ---------------- persistent controller ----------------
__global__ void __launch_bounds__(NT, 1)
nas_persist(const int*   __restrict__ input_id,
            const float* __restrict__ Wout,
            const float* __restrict__ bout,
            float* __restrict__ out) {
    __shared__ __align__(16) float sV[2 * HH];   // [h1(t) ; h2(t-1)]
    __shared__ float sWo[SS * UPB];
    __shared__ float sG[48];

    const int tid  = threadIdx.x;
    const int w    = tid >> 5;
    const int lane = tid & 31;
    const int b    = blockIdx.x;
    const int u0   = b * UPB;

    const int l0   = 2 * w;
    const int gate = l0 / 12;
    const int j0   = l0 % 12;
    const int grow = gate * HH + u0 + j0;
    const __nv_bfloat16* w2base = g_w2cat + (size_t)grow * (2 * HH);
    const int r1row = b * 48 + l0;
    const __nv_bfloat16* w1base = g_whh1 + (size_t)r1row * HH;

    for (int t = 0; t < TT; t++) {
        const int par = t & 1;
        const int rb = t % 3, wb = (t + 1) % 3, zb = (t + 2) % 3;

        // ---- loads (all argmax-independent) ----
        float lg = 0.f;
        if (t > 0) lg = g_log3[rb][lane * LSTR] + bout[(t - 1) * SS + lane];
        float h2r[2], a0[2], a1[2], a2[2], a3[2], cc[2];
        #pragma unroll
        for (int k = 0; k < 2; k++) {
            int u = tid + k * NT;
            h2r[k] = g_h2[par][u];
            if (t > 0) {
                a0[k] = g_g1[par][u];          a1[k] = g_g1[par][HH + u];
                a2[k] = g_g1[par][2 * HH + u]; a3[k] = g_g1[par][3 * HH + u];
                cc[k] = g_c1[par][u];
            }
        }
        if (tid < SS * UPB) {   // fp32 head slice for this block's units
            int s = tid / UPB, j = tid % UPB;
            sWo[tid] = __ldg(&Wout[((size_t)t * SS + s) * HH + u0 + j]);
        }

        // ---- stage h2(t-1) ----
        #pragma unroll
        for (int k = 0; k < 2; k++) sV[HH + tid + k * NT] = h2r[k];
        __syncthreads();

        // ---- dotA: W_hh2 @ h2(t-1); loads fly while softmax (shfl-only) runs
        float acc[2] = {0.f, 0.f};
        dot2_acc<6>(w2base + HH, 2 * HH, sV + HH, lane, acc);

        // ---- per-warp redundant softmax/argmax of step t-1 (fused max+argmax)
        int sid = 0;
        if (t > 0) {
            float v = lg;
            float bv = v; int bi = lane;
            #pragma unroll
            for (int o = 16; o; o >>= 1) {
                float ov = __shfl_xor_sync(0xffffffffu, bv, o);
                int   oi = __shfl_xor_sync(0xffffffffu, bi, o);
                if (ov > bv || (ov == bv && oi < bi)) { bv = ov; bi = oi; }
            }
            // bv = max, bi = argmax (first-index tie-break)
            float e = expf(v - bv), se = e;
            #pragma unroll
            for (int o = 16; o; o >>= 1) se += __shfl_xor_sync(0xffffffffu, se, o);
            float lse = bv + logf(se);
            if (b == 0 && w == 0) out[(t - 1) * SS + lane] = v - lse;
            sid = ((t - 1) & 3) * SS + bi;
        }

        // ---- build h1(t) redundantly; own c1 slice ----
        if (t == 0) {
            int id0 = *input_id;
            const float* xp = g_xproj + (size_t)id0 * G4;
            #pragma unroll
            for (int k = 0; k < 2; k++) {
                int u = tid + k * NT;
                float gi = xp[u], gg = xp[2 * HH + u], go = xp[3 * HH + u];
                float cn = fsigm(gi) * ftanh(gg);
                sV[u] = fsigm(go) * ftanh(cn);
                if (u >= u0 && u < u0 + UPB) g_c1[1][u] = cn;
            }
        } else {
            const float* xp = g_xproj + (size_t)sid * G4;
            #pragma unroll
            for (int k = 0; k < 2; k++) {
                int u = tid + k * NT;
                float gi = a0[k] + xp[u];
                float gf = a1[k] + xp[HH + u];
                float gg = a2[k] + xp[2 * HH + u];
                float go = a3[k] + xp[3 * HH + u];
                float cn = fsigm(gf) * cc[k] + fsigm(gi) * ftanh(gg);
                sV[u] = fsigm(go) * ftanh(cn);
                if (u >= u0 && u < u0 + UPB) g_c1[par ^ 1][u] = cn;
            }
        }
        __syncthreads();

        // ---- FUSED dotB: W_ih2 rows + W_hh1 rows, one pass over h1(t) ----
        float r1[2] = {0.f, 0.f};
        dot2x2_acc<6>(w2base, 2 * HH, w1base, HH, sV, lane, acc, r1);
        acc[0] = warpsum(acc[0]);
        acc[1] = warpsum(acc[1]);
        r1[0]  = warpsum(r1[0]);
        r1[1]  = warpsum(r1[1]);
        if (lane == 0) {
            sG[l0]     = acc[0] + g_b2sum[grow];
            sG[l0 + 1] = acc[1] + g_b2sum[grow + 1];
            g_g1[par ^ 1][r1row]     = r1[0];
            g_g1[par ^ 1][r1row + 1] = r1[1];
        }
        __syncthreads();

        // ---- finalize own h2 units + partial logits -> spread atomics ----
        if (w == 0) {
            float hn = 0.f;
            if (lane < UPB) {
                int u = u0 + lane;
                float gi = sG[lane], gf = sG[12 + lane], gg = sG[24 + lane], go = sG[36 + lane];
                float c  = g_c2[u];
                float cn = fsigm(gf) * c + fsigm(gi) * ftanh(gg);
                g_c2[u]          = cn;
                hn               = fsigm(go) * ftanh(cn);
                g_h2[par ^ 1][u] = hn;
            }
            float p = 0.f;
            #pragma unroll
            for (int j = 0; j < UPB; j++) {
                float hj = __shfl_sync(0xffffffffu, hn, j);
                p = fmaf(sWo[lane * UPB + j], hj, p);
            }
            atomicAdd(&g_log3[wb][lane * LSTR], p);
        }
        if (b == 0 && w == 1) g_log3[zb][lane * LSTR] = 0.0f;  // recycle buffer

        grid_sync(b, (unsigned)(t + 1));
    }

    // epilogue: logp(47) from g_log3[48%3 = 0]
    if (b == 0 && w == 0) {
        float v = g_log3[0][lane * LSTR] + bout[47 * SS + lane];
        float m = v;
        #pragma unroll
        for (int o = 16; o; o >>= 1) m = fmaxf(m, __shfl_xor_sync(0xffffffffu, m, o));
        float e = expf(v - m), se = e;
        #pragma unroll
        for (int o = 16; o; o >>= 1) se += __shfl_xor_sync(0xffffffffu, se, o);
        float lse = m + logf(se);
        out[47 * SS + lane] = v - lse;
    }
}

extern "C" void kernel_launch(void* const* d_in, const int* in_sizes, int n_in,
                              void* d_out, int out_size) {
    const int*   input_id = (const int*)  d_in[0];
    const float* emb      = (const float*)d_in[1];
    const float* W_ih1    = (const float*)d_in[2];
    const float* W_hh1    = (const float*)d_in[3];
    const float* b_ih1    = (const float*)d_in[4];
    const float* b_hh1    = (const float*)d_in[5];
    const float* W_ih2    = (const float*)d_in[6];
    const float* W_hh2    = (const float*)d_in[7];
    const float* b_ih2    = (const float*)d_in[8];
    const float* b_hh2    = (const float*)d_in[9];
    const float* W_out    = (const float*)d_in[10];
    const float* b_out    = (const float*)d_in[11];
    float* out = (float*)d_out;

    __nv_bfloat16* w2cat_d; cudaGetSymbolAddress((void**)&w2cat_d, g_w2cat);
    __nv_bfloat16* whh1_d;  cudaGetSymbolAddress((void**)&whh1_d,  g_whh1);

    dim3 prep_grid((WELEM / 8 + 511) / 512, 4);   // jobs 0-2: cvt; job 3: xproj
    init_kernel<<<1, 1024>>>(b_ih2, b_hh2);
    prep_kernel<<<prep_grid, 512>>>(W_ih2, W_hh2, W_hh1, w2cat_d, whh1_d,
                                    W_ih1, b_ih1, b_hh1, emb);
    nas_persist<<<NB, NT>>>(input_id, W_out, b_out, out);
}

// round 11
// speedup vs baseline: 2.0918x; 1.1925x over previous
#include <cuda_runtime.h>
#include <cuda_bf16.h>
#include <math.h>

#define E    512
#define HH   1536
#define G4   6144
#define SS   32
#define TT   48
#define NV   128
#define NB   128       // persistent blocks (1/SM)
#define NT   768       // 24 warps
#define UPB  12        // h2/c2 units per block
#define LSTR 64        // logit slot stride (256B)
#define FSTR 32        // flag slot stride (128B)
#define WELEM (G4 * HH)

// ---------------- persistent device state ----------------
__device__ float          g_xproj[NV * G4];            // W_ih1@emb[v] + b_ih1 + b_hh1
__device__ __nv_bfloat16  g_w2cat[(size_t)G4 * 2 * HH];// [W_ih2 | W_hh2] rows of 3072
__device__ __nv_bfloat16  g_whh1[WELEM];
__device__ float          g_c1[2][HH];
__device__ float          g_c2[HH];
__device__ float          g_h2[2][HH];
__device__ float          g_g1[2][G4];                 // W_hh1 @ h1(t), double buffered
__device__ float          g_log3[3][SS * LSTR];        // triple-buffered padded logits
__device__ unsigned       g_flags[NB * FSTR];          // monotonic epochs (never reset)

__device__ __forceinline__ float fsigm(float x) {
    return __fdividef(1.0f, 1.0f + __expf(-x));
}
__device__ __forceinline__ float ftanh(float x) {
    x = fminf(fmaxf(x, -15.0f), 15.0f);
    float e = __expf(2.0f * x);
    return __fdividef(e - 1.0f, e + 1.0f);
}
__device__ __forceinline__ float warpsum(float v) {
    #pragma unroll
    for (int o = 16; o; o >>= 1) v += __shfl_down_sync(0xffffffffu, v, o);
    return v;
}

// 2 rows from one base, vector from smem; accumulate (no init)
template<int SEGS>
__device__ __forceinline__ void dot2_acc(const __nv_bfloat16* __restrict__ base,
                                         size_t stride, const float* __restrict__ sv,
                                         int lane, float* acc) {
    #pragma unroll
    for (int j = 0; j < SEGS; j++) {
        int seg = lane + 32 * j;
        const float4* v = (const float4*)(sv + seg * 8);
        float4 v0 = v[0], v1 = v[1];
        #pragma unroll
        for (int r = 0; r < 2; r++) {
            uint4 a = __ldg((const uint4*)(base + r * stride) + seg);
            float2 p;
            p = __bfloat1622float2(*(const __nv_bfloat162*)&a.x);
            acc[r] = fmaf(p.x, v0.x, acc[r]); acc[r] = fmaf(p.y, v0.y, acc[r]);
            p = __bfloat1622float2(*(const __nv_bfloat162*)&a.y);
            acc[r] = fmaf(p.x, v0.z, acc[r]); acc[r] = fmaf(p.y, v0.w, acc[r]);
            p = __bfloat1622float2(*(const __nv_bfloat162*)&a.z);
            acc[r] = fmaf(p.x, v1.x, acc[r]); acc[r] = fmaf(p.y, v1.y, acc[r]);
            p = __bfloat1622float2(*(const __nv_bfloat162*)&a.w);
            acc[r] = fmaf(p.x, v1.z, acc[r]); acc[r] = fmaf(p.y, v1.w, acc[r]);
        }
    }
}

// FUSED: 2 rows from baseA + 2 rows from baseB, ONE vector pass
template<int SEGS>
__device__ __forceinline__ void dot2x2_acc(const __nv_bfloat16* __restrict__ baseA,
                                           size_t strideA,
                                           const __nv_bfloat16* __restrict__ baseB,
                                           size_t strideB,
                                           const float* __restrict__ sv, int lane,
                                           float* accA, float* accB) {
    #pragma unroll
    for (int j = 0; j < SEGS; j++) {
        int seg = lane + 32 * j;
        const float4* v = (const float4*)(sv + seg * 8);
        float4 v0 = v[0], v1 = v[1];
        uint4 a0 = __ldg((const uint4*)(baseA) + seg);
        uint4 a1 = __ldg((const uint4*)(baseA + strideA) + seg);
        uint4 b0 = __ldg((const uint4*)(baseB) + seg);
        uint4 b1 = __ldg((const uint4*)(baseB + strideB) + seg);
        float2 p;
        #define ACC8(acc, q) \
            p = __bfloat1622float2(*(const __nv_bfloat162*)&q.x); \
            acc = fmaf(p.x, v0.x, acc); acc = fmaf(p.y, v0.y, acc); \
            p = __bfloat1622float2(*(const __nv_bfloat162*)&q.y); \
            acc = fmaf(p.x, v0.z, acc); acc = fmaf(p.y, v0.w, acc); \
            p = __bfloat1622float2(*(const __nv_bfloat162*)&q.z); \
            acc = fmaf(p.x, v1.x, acc); acc = fmaf(p.y, v1.y, acc); \
            p = __bfloat1622float2(*(const __nv_bfloat162*)&q.w); \
            acc = fmaf(p.x, v1.z, acc); acc = fmaf(p.y, v1.w, acc);
        ACC8(accA[0], a0)
        ACC8(accA[1], a1)
        ACC8(accB[0], b0)
        ACC8(accB[1], b1)
        #undef ACC8
    }
}

// symmetric grid barrier: every block arrives on its own padded flag,
// first NB threads of every block poll all flags; no central release word.
__device__ __forceinline__ void grid_sync(int b, unsigned ep) {
    __threadfence();                 // release: prior writes visible device-wide
    __syncthreads();
    if (threadIdx.x == 0)
        *(volatile unsigned*)&g_flags[b * FSTR] = ep;
    if (threadIdx.x < NB) {
        volatile unsigned* f = &g_flags[threadIdx.x * FSTR];
        while ((int)(*f - ep) < 0) { __nanosleep(64); }
    }
    __syncthreads();
    __threadfence();                 // acquire: per-thread; invalidates stale L1
}

// ================== the one and only kernel ==================
__global__ void __launch_bounds__(NT, 1)
nas_all(const int*   __restrict__ input_id,
        const float* __restrict__ emb,
        const float* __restrict__ Wih1,
        const float* __restrict__ Whh1f,
        const float* __restrict__ bih1, const float* __restrict__ bhh1,
        const float* __restrict__ Wih2f,
        const float* __restrict__ Whh2f,
        const float* __restrict__ bih2, const float* __restrict__ bhh2,
        const float* __restrict__ Wout,
        const float* __restrict__ bout,
        float* __restrict__ out) {
    __shared__ __align__(16) float sMem[16 * (E + 8)];   // 33.3 KB, aliased
    float* sV  = sMem;               // loop: [h1 ; h2]  (3072 floats)
    float* sWo = sMem + 2 * HH;      // loop: head slice (384)
    float* sG  = sMem + 2 * HH + SS * UPB;   // loop: gates (48)
    __shared__ unsigned sBase;

    const int tid  = threadIdx.x;
    const int w    = tid >> 5;
    const int lane = tid & 31;
    const int b    = blockIdx.x;
    const int u0   = b * UPB;

    // warp row assignments for the loop
    const int l0   = 2 * w;
    const int gate = l0 / 12;
    const int j0   = l0 % 12;
    const int grow = gate * HH + u0 + j0;
    const __nv_bfloat16* w2base = g_w2cat + (size_t)grow * (2 * HH);
    const int r1row = b * 48 + l0;
    const __nv_bfloat16* w1base = g_whh1 + (size_t)r1row * HH;
    const float bsum0 = __ldg(&bih2[grow])     + __ldg(&bhh2[grow]);
    const float bsum1 = __ldg(&bih2[grow + 1]) + __ldg(&bhh2[grow + 1]);

    // ---- epoch base (flags are monotonic across graph replays) ----
    if (tid == 0) sBase = g_flags[b * FSTR];
    __syncthreads();
    const unsigned base = sBase;

    // ======== PROLOGUE (distributed by block) ========
    // zero own state slices
    if (tid < UPB) { g_c2[u0 + tid] = 0.f; g_h2[0][u0 + tid] = 0.f; }

    // bf16-convert own 48 rows of W_ih2 / W_hh2 (into concat) and W_hh1
    {
        const size_t r0 = (size_t)b * 48;
        #pragma unroll
        for (int m = 0; m < 3; m++) {
            const float* src = (m == 0) ? Wih2f : (m == 1) ? Whh2f : Whh1f;
            for (int idx = tid; idx < 48 * HH / 8; idx += NT) {
                size_t e = (size_t)idx * 8;
                size_t row = r0 + e / HH, col = e % HH;
                const float* s = src + row * HH + col;
                float4 a = *(const float4*)s;
                float4 c = *(const float4*)(s + 4);
                __nv_bfloat162 q0 = __floats2bfloat162_rn(a.x, a.y);
                __nv_bfloat162 q1 = __floats2bfloat162_rn(a.z, a.w);
                __nv_bfloat162 q2 = __floats2bfloat162_rn(c.x, c.y);
                __nv_bfloat162 q3 = __floats2bfloat162_rn(c.z, c.w);
                uint4 o;
                o.x = *(unsigned*)&q0; o.y = *(unsigned*)&q1;
                o.z = *(unsigned*)&q2; o.w = *(unsigned*)&q3;
                __nv_bfloat16* d = (m == 2)
                    ? (g_whh1 + row * HH + col)
                    : (g_w2cat + row * (2 * HH) + (m == 1 ? HH : 0) + col);
                *(uint4*)d = o;
            }
        }
    }

    // xproj: own rows r, r+1 for all 128 embeddings (register-tiled)
    {
        const int r = b * 48 + w * 2;
        float4 Wa[4], Wb[4];
        const float4* wra = (const float4*)(Wih1 + (size_t)r * E);
        const float4* wrb = (const float4*)(Wih1 + (size_t)(r + 1) * E);
        #pragma unroll
        for (int i = 0; i < 4; i++) {
            Wa[i] = __ldg(&wra[lane * 4 + i]);
            Wb[i] = __ldg(&wrb[lane * 4 + i]);
        }
        const float bs0 = __ldg(&bih1[r])     + __ldg(&bhh1[r]);
        const float bs1 = __ldg(&bih1[r + 1]) + __ldg(&bhh1[r + 1]);

        for (int c = 0; c < NV / 16; c++) {
            __syncthreads();
            for (int idx = tid; idx < 16 * (E / 4); idx += NT) {
                int v = idx >> 7, e4 = idx & 127;
                float4 d = __ldg((const float4*)(emb + (size_t)(c * 16 + v) * E) + e4);
                *(float4*)&sMem[v * (E + 8) + e4 * 4] = d;
            }
            __syncthreads();
            #pragma unroll 2
            for (int v = 0; v < 16; v++) {
                const float* ev = &sMem[v * (E + 8) + lane * 16];
                float a0 = 0.f, a1 = 0.f;
                #pragma unroll
                for (int i = 0; i < 4; i++) {
                    float4 x = *(const float4*)(ev + 4 * i);
                    a0 = fmaf(Wa[i].x, x.x, a0); a0 = fmaf(Wa[i].y, x.y, a0);
                    a0 = fmaf(Wa[i].z, x.z, a0); a0 = fmaf(Wa[i].w, x.w, a0);
                    a1 = fmaf(Wb[i].x, x.x, a1); a1 = fmaf(Wb[i].y, x.y, a1);
                    a1 = fmaf(Wb[i].z, x.z, a1); a1 = fmaf(Wb[i].w, x.w, a1);
                }
                a0 = warpsum(a0);
                a1 = warpsum(a1);
                if (lane == 0) {
                    g_xproj[(size_t)(c * 16 + v) * G4 + r]     = a0 + bs0;
                    g_xproj[(size_t)(c * 16 + v) * G4 + r + 1] = a1 + bs1;
                }
            }
        }
    }

    grid_sync(b, base + 1);

    // ======== 48-step controller loop ========
    for (int t = 0; t < TT; t++) {
        const int par = t & 1;
        const int rb = t % 3, wb = (t + 1) % 3, zb = (t + 2) % 3;

        // ---- loads (all argmax-independent) ----
        float lg = 0.f;
        if (t > 0) lg = g_log3[rb][lane * LSTR] + bout[(t - 1) * SS + lane];
        float h2r[2], a0[2], a1[2], a2[2], a3[2], cc[2];
        #pragma unroll
        for (int k = 0; k < 2; k++) {
            int u = tid + k * NT;
            h2r[k] = g_h2[par][u];
            if (t > 0) {
                a0[k] = g_g1[par][u];          a1[k] = g_g1[par][HH + u];
                a2[k] = g_g1[par][2 * HH + u]; a3[k] = g_g1[par][3 * HH + u];
                cc[k] = g_c1[par][u];
            }
        }
        if (tid < SS * UPB) {   // fp32 head slice for this block's units
            int s = tid / UPB, j = tid % UPB;
            sWo[tid] = __ldg(&Wout[((size_t)t * SS + s) * HH + u0 + j]);
        }

        // ---- stage h2(t-1) ----
        #pragma unroll
        for (int k = 0; k < 2; k++) sV[HH + tid + k * NT] = h2r[k];
        __syncthreads();

        // ---- dotA: W_hh2 @ h2(t-1); loads fly while softmax (shfl-only) runs
        float acc[2] = {0.f, 0.f};
        dot2_acc<6>(w2base + HH, 2 * HH, sV + HH, lane, acc);

        // ---- per-warp redundant softmax/argmax of step t-1 (fused max+argmax)
        int sid = 0;
        if (t > 0) {
            float v = lg;
            float bv = v; int bi = lane;
            #pragma unroll
            for (int o = 16; o; o >>= 1) {
                float ov = __shfl_xor_sync(0xffffffffu, bv, o);
                int   oi = __shfl_xor_sync(0xffffffffu, bi, o);
                if (ov > bv || (ov == bv && oi < bi)) { bv = ov; bi = oi; }
            }
            float e = expf(v - bv), se = e;
            #pragma unroll
            for (int o = 16; o; o >>= 1) se += __shfl_xor_sync(0xffffffffu, se, o);
            float lse = bv + logf(se);
            if (b == 0 && w == 0) out[(t - 1) * SS + lane] = v - lse;
            sid = ((t - 1) & 3) * SS + bi;
        }

        // ---- build h1(t) redundantly; own c1 slice ----
        if (t == 0) {
            int id0 = *input_id;
            const float* xp = g_xproj + (size_t)id0 * G4;
            #pragma unroll
            for (int k = 0; k < 2; k++) {
                int u = tid + k * NT;
                float gi = xp[u], gg = xp[2 * HH + u], go = xp[3 * HH + u];
                float cn = fsigm(gi) * ftanh(gg);
                sV[u] = fsigm(go) * ftanh(cn);
                if (u >= u0 && u < u0 + UPB) g_c1[1][u] = cn;
            }
        } else {
            const float* xp = g_xproj + (size_t)sid * G4;
            #pragma unroll
            for (int k = 0; k < 2; k++) {
                int u = tid + k * NT;
                float gi = a0[k] + xp[u];
                float gf = a1[k] + xp[HH + u];
                float gg = a2[k] + xp[2 * HH + u];
                float go = a3[k] + xp[3 * HH + u];
                float cn = fsigm(gf) * cc[k] + fsigm(gi) * ftanh(gg);
                sV[u] = fsigm(go) * ftanh(cn);
                if (u >= u0 && u < u0 + UPB) g_c1[par ^ 1][u] = cn;
            }
        }
        __syncthreads();

        // ---- FUSED dotB: W_ih2 rows + W_hh1 rows, one pass over h1(t) ----
        float r1[2] = {0.f, 0.f};
        dot2x2_acc<6>(w2base, 2 * HH, w1base, HH, sV, lane, acc, r1);
        acc[0] = warpsum(acc[0]);
        acc[1] = warpsum(acc[1]);
        r1[0]  = warpsum(r1[0]);
        r1[1]  = warpsum(r1[1]);
        if (lane == 0) {
            sG[l0]     = acc[0] + bsum0;
            sG[l0 + 1] = acc[1] + bsum1;
            g_g1[par ^ 1][r1row]     = r1[0];
            g_g1[par ^ 1][r1row + 1] = r1[1];
        }
        __syncthreads();

        // ---- finalize own h2 units + partial logits -> spread atomics ----
        if (w == 0) {
            float hn = 0.f;
            if (lane < UPB) {
                int u = u0 + lane;
                float gi = sG[lane], gf = sG[12 + lane], gg = sG[24 + lane], go = sG[36 + lane];
                float c  = g_c2[u];
                float cn = fsigm(gf) * c + fsigm(gi) * ftanh(gg);
                g_c2[u]          = cn;
                hn               = fsigm(go) * ftanh(cn);
                g_h2[par ^ 1][u] = hn;
            }
            float p = 0.f;
            #pragma unroll
            for (int j = 0; j < UPB; j++) {
                float hj = __shfl_sync(0xffffffffu, hn, j);
                p = fmaf(sWo[lane * UPB + j], hj, p);
            }
            atomicAdd(&g_log3[wb][lane * LSTR], p);
        }
        if (b == 0 && w == 1) g_log3[zb][lane * LSTR] = 0.0f;  // recycle buffer

        grid_sync(b, base + 2 + (unsigned)t);
    }

    // epilogue: logp(47) from g_log3[48%3 = 0]
    if (b == 0 && w == 0) {
        float v = g_log3[0][lane * LSTR] + bout[47 * SS + lane];
        float m = v;
        #pragma unroll
        for (int o = 16; o; o >>= 1) m = fmaxf(m, __shfl_xor_sync(0xffffffffu, m, o));
        float e = expf(v - m), se = e;
        #pragma unroll
        for (int o = 16; o; o >>= 1) se += __shfl_xor_sync(0xffffffffu, se, o);
        float lse = m + logf(se);
        out[47 * SS + lane] = v - lse;
    }
}

extern "C" void kernel_launch(void* const* d_in, const int* in_sizes, int n_in,
                              void* d_out, int out_size) {
    const int*   input_id = (const int*)  d_in[0];
    const float* emb      = (const float*)d_in[1];
    const float* W_ih1    = (const float*)d_in[2];
    const float* W_hh1    = (const float*)d_in[3];
    const float* b_ih1    = (const float*)d_in[4];
    const float* b_hh1    = (const float*)d_in[5];
    const float* W_ih2    = (const float*)d_in[6];
    const float* W_hh2    = (const float*)d_in[7];
    const float* b_ih2    = (const float*)d_in[8];
    const float* b_hh2    = (const float*)d_in[9];
    const float* W_out    = (const float*)d_in[10];
    const float* b_out    = (const float*)d_in[11];
    float* out = (float*)d_out;

    nas_all<<<NB, NT>>>(input_id, emb, W_ih1, W_hh1, b_ih1, b_hh1,
                        W_ih2, W_hh2, b_ih2, b_hh2, W_out, b_out, out);
}